// round 4
// baseline (speedup 1.0000x reference)
#include <cuda_runtime.h>

// ---------------------------------------------------------------------------
// SparseMPNNLayer: fused fp32 implementation
//   pass1: msg = MLP([h_v[src], h_u[dst], e_feat]) -> atomic scatter to m_u[dst]
//          deg[src] += 1
//   node1: h_u_out = MLP([h_u, m_u/S])              (written to d_out+NV*64)
//   pass2: msg = MLP([h_u_out[dst], h_v[src], e_feat]) -> scatter to m_v[src]
//   node2: h_v_out = MLP([h_v, m_v/max(deg,1)])     (written to d_out)
// Edge indices are int32 (harness dtype set is {float32, int32, bfloat16}).
// ---------------------------------------------------------------------------

#define TPB 256
constexpr int HD = 64;
constexpr int MAXN = 100000;

// Scratch (device globals: allowed; runtime alloc is not)
__device__ float g_m_u[(size_t)MAXN * HD];
__device__ float g_m_v[(size_t)MAXN * HD];
__device__ float g_deg[MAXN];

// SMEM float counts
constexpr int EDGE_SMEM_FLOATS = 192*128 + 128*64 + 128 + 64 + 64*192 + 64*128;
constexpr int NODE_SMEM_FLOATS = 128*64 + 64*64 + 64 + 64 + 64*128 + 64*64;
constexpr int EDGE_SMEM_BYTES = EDGE_SMEM_FLOATS * 4;   // 213760
constexpr int NODE_SMEM_BYTES = NODE_SMEM_FLOATS * 4;   // 98816

// ---------------------------------------------------------------------------
// Edge MLP: x = [A[idxA[e]], B[idxB[e]], EF[e]] (192) -> relu(x@W1+b1) (128)
//           -> @W2+b2 (64) -> atomicAdd into accum[idxOut[e]]
// CTA: 256 threads, persistent, tile = 64 edges. Warp tile: 8 edges x 128 hid.
// ---------------------------------------------------------------------------
__global__ void __launch_bounds__(TPB) edge_mlp_kernel(
    const float* __restrict__ A, const int* __restrict__ idxA,
    const float* __restrict__ B, const int* __restrict__ idxB,
    const float* __restrict__ EF,
    const int* __restrict__ idxOut,
    const float* __restrict__ W1, const float* __restrict__ b1,
    const float* __restrict__ W2, const float* __restrict__ b2,
    float* __restrict__ accum, float* __restrict__ deg,
    int E)
{
    extern __shared__ float sm[];
    float* sW1 = sm;                    // 192*128
    float* sW2 = sW1 + 192*128;         // 128*64
    float* sb1 = sW2 + 128*64;          // 128
    float* sb2 = sb1 + 128;             // 64
    float* sX  = sb2 + 64;              // 64*192
    float* sH  = sX + 64*192;           // 64*128

    const int tid = threadIdx.x;
    for (int i = tid; i < (192*128)/4; i += TPB)
        ((float4*)sW1)[i] = ((const float4*)W1)[i];
    for (int i = tid; i < (128*64)/4; i += TPB)
        ((float4*)sW2)[i] = ((const float4*)W2)[i];
    if (tid < 128) sb1[tid] = b1[tid];
    if (tid < 64)  sb2[tid] = b2[tid];

    const int warp = tid >> 5, lane = tid & 31;
    const int ntiles = (E + 63) >> 6;

    for (int tile = blockIdx.x; tile < ntiles; tile += gridDim.x) {
        const int base = tile << 6;
        __syncthreads();  // smem reuse barrier (also covers weight staging)

        // ---- stage X tile [64][192] ----
        {
            const int el = tid >> 2, q = tid & 3;   // 64 edges x 4 chunks
            const int e = base + el;
            if (e < E) {
                const int ia = idxA[e];
                const int ib = idxB[e];
                const float4* ra = (const float4*)(A  + (size_t)ia * HD) + q*4;
                const float4* rb = (const float4*)(B  + (size_t)ib * HD) + q*4;
                const float4* re = (const float4*)(EF + (size_t)e * HD) + q*4;
                float4* xr = (float4*)(sX + el * 192);
                #pragma unroll
                for (int i = 0; i < 4; i++) xr[q*4 + i]      = ra[i];
                #pragma unroll
                for (int i = 0; i < 4; i++) xr[16 + q*4 + i] = rb[i];
                #pragma unroll
                for (int i = 0; i < 4; i++) xr[32 + q*4 + i] = re[i];
            }
        }
        __syncthreads();

        // ---- GEMM1: [8 edges] x [128 hidden], lane owns hidden 4*lane..+3 ----
        const int eb = warp * 8;
        float acc[8][4];
        {
            const float4 bv = *(const float4*)(sb1 + 4*lane);
            #pragma unroll
            for (int e = 0; e < 8; e++) {
                acc[e][0]=bv.x; acc[e][1]=bv.y; acc[e][2]=bv.z; acc[e][3]=bv.w;
            }
        }
        #pragma unroll 1
        for (int k = 0; k < 192; k += 4) {
            float4 xv[8];
            #pragma unroll
            for (int e = 0; e < 8; e++)
                xv[e] = *(const float4*)(sX + (eb + e)*192 + k);  // broadcast
            #pragma unroll
            for (int kk = 0; kk < 4; kk++) {
                const float4 w = *(const float4*)(sW1 + (k + kk)*128 + 4*lane);
                #pragma unroll
                for (int e = 0; e < 8; e++) {
                    const float x = (kk==0)?xv[e].x:(kk==1)?xv[e].y:(kk==2)?xv[e].z:xv[e].w;
                    acc[e][0] = fmaf(x, w.x, acc[e][0]);
                    acc[e][1] = fmaf(x, w.y, acc[e][1]);
                    acc[e][2] = fmaf(x, w.z, acc[e][2]);
                    acc[e][3] = fmaf(x, w.w, acc[e][3]);
                }
            }
        }
        #pragma unroll
        for (int e = 0; e < 8; e++) {
            float4 h = make_float4(fmaxf(acc[e][0], 0.f), fmaxf(acc[e][1], 0.f),
                                   fmaxf(acc[e][2], 0.f), fmaxf(acc[e][3], 0.f));
            *(float4*)(sH + (eb + e)*128 + 4*lane) = h;
        }
        __syncthreads();

        // ---- GEMM2: [8 edges] x [64 out], lane owns out 2*lane..+1 ----
        float a2[8][2];
        {
            const float2 bv = *(const float2*)(sb2 + 2*lane);
            #pragma unroll
            for (int e = 0; e < 8; e++) { a2[e][0]=bv.x; a2[e][1]=bv.y; }
        }
        #pragma unroll 1
        for (int j = 0; j < 128; j += 4) {
            float4 hv[8];
            #pragma unroll
            for (int e = 0; e < 8; e++)
                hv[e] = *(const float4*)(sH + (eb + e)*128 + j);  // broadcast
            #pragma unroll
            for (int jj = 0; jj < 4; jj++) {
                const float2 w = *(const float2*)(sW2 + (j + jj)*64 + 2*lane);
                #pragma unroll
                for (int e = 0; e < 8; e++) {
                    const float h = (jj==0)?hv[e].x:(jj==1)?hv[e].y:(jj==2)?hv[e].z:hv[e].w;
                    a2[e][0] = fmaf(h, w.x, a2[e][0]);
                    a2[e][1] = fmaf(h, w.y, a2[e][1]);
                }
            }
        }

        // ---- scatter ----
        #pragma unroll
        for (int e = 0; e < 8; e++) {
            const int ge = base + eb + e;
            if (ge < E) {
                const int d = idxOut[ge];
                atomicAdd(accum + (size_t)d*HD + 2*lane,     a2[e][0]);
                atomicAdd(accum + (size_t)d*HD + 2*lane + 1, a2[e][1]);
            }
        }
        if (deg != nullptr && lane < 8) {
            const int ge = base + eb + lane;
            if (ge < E) atomicAdd(deg + idxA[ge], 1.0f);
        }
    }
}

// ---------------------------------------------------------------------------
// Node MLP: x = [self[i], msum[i]*scale] (128) -> relu(x@W1+b1) (64) -> @W2+b2
//   scale = 1/S (Sp != null) or 1/max(deg[i],1)
// ---------------------------------------------------------------------------
__global__ void __launch_bounds__(TPB) node_mlp_kernel(
    const float* __restrict__ selfF, const float* __restrict__ msum,
    const float* __restrict__ deg, const int* __restrict__ Sp,
    const float* __restrict__ W1, const float* __restrict__ b1,
    const float* __restrict__ W2, const float* __restrict__ b2,
    float* __restrict__ out, int N)
{
    extern __shared__ float sm[];
    float* sW1 = sm;            // 128*64
    float* sW2 = sW1 + 128*64;  // 64*64
    float* sb1 = sW2 + 64*64;   // 64
    float* sb2 = sb1 + 64;      // 64
    float* sX  = sb2 + 64;      // 64*128
    float* sH  = sX + 64*128;   // 64*64

    const int tid = threadIdx.x;
    for (int i = tid; i < (128*64)/4; i += TPB)
        ((float4*)sW1)[i] = ((const float4*)W1)[i];
    for (int i = tid; i < (64*64)/4; i += TPB)
        ((float4*)sW2)[i] = ((const float4*)W2)[i];
    if (tid < 64) { sb1[tid] = b1[tid]; sb2[tid] = b2[tid]; }

    const float invS = (Sp != nullptr) ? (1.0f / (float)(*Sp)) : 0.0f;

    const int warp = tid >> 5, lane = tid & 31;
    const int ntiles = (N + 63) >> 6;

    for (int tile = blockIdx.x; tile < ntiles; tile += gridDim.x) {
        const int base = tile << 6;
        __syncthreads();

        // ---- stage X tile [64][128] ----
        {
            const int r = tid >> 2, q = tid & 3;
            const int i = base + r;
            if (i < N) {
                const float sc = (Sp != nullptr) ? invS : (1.0f / fmaxf(deg[i], 1.0f));
                const float4* rs = (const float4*)(selfF + (size_t)i * HD) + q*4;
                const float4* rm = (const float4*)(msum  + (size_t)i * HD) + q*4;
                float4* xr = (float4*)(sX + r * 128);
                #pragma unroll
                for (int t = 0; t < 4; t++) xr[q*4 + t] = rs[t];
                #pragma unroll
                for (int t = 0; t < 4; t++) {
                    float4 v = rm[t];
                    v.x *= sc; v.y *= sc; v.z *= sc; v.w *= sc;
                    xr[16 + q*4 + t] = v;
                }
            }
        }
        __syncthreads();

        const int rb = warp * 8;
        float acc[8][2];
        {
            const float2 bv = *(const float2*)(sb1 + 2*lane);
            #pragma unroll
            for (int e = 0; e < 8; e++) { acc[e][0]=bv.x; acc[e][1]=bv.y; }
        }
        #pragma unroll 1
        for (int k = 0; k < 128; k += 4) {
            float4 xv[8];
            #pragma unroll
            for (int e = 0; e < 8; e++)
                xv[e] = *(const float4*)(sX + (rb + e)*128 + k);
            #pragma unroll
            for (int kk = 0; kk < 4; kk++) {
                const float2 w = *(const float2*)(sW1 + (k + kk)*64 + 2*lane);
                #pragma unroll
                for (int e = 0; e < 8; e++) {
                    const float x = (kk==0)?xv[e].x:(kk==1)?xv[e].y:(kk==2)?xv[e].z:xv[e].w;
                    acc[e][0] = fmaf(x, w.x, acc[e][0]);
                    acc[e][1] = fmaf(x, w.y, acc[e][1]);
                }
            }
        }
        #pragma unroll
        for (int e = 0; e < 8; e++) {
            float2 h = make_float2(fmaxf(acc[e][0], 0.f), fmaxf(acc[e][1], 0.f));
            *(float2*)(sH + (rb + e)*64 + 2*lane) = h;
        }
        __syncthreads();

        float a2[8][2];
        {
            const float2 bv = *(const float2*)(sb2 + 2*lane);
            #pragma unroll
            for (int e = 0; e < 8; e++) { a2[e][0]=bv.x; a2[e][1]=bv.y; }
        }
        #pragma unroll 1
        for (int j = 0; j < 64; j += 4) {
            float4 hv[8];
            #pragma unroll
            for (int e = 0; e < 8; e++)
                hv[e] = *(const float4*)(sH + (rb + e)*64 + j);
            #pragma unroll
            for (int jj = 0; jj < 4; jj++) {
                const float2 w = *(const float2*)(sW2 + (j + jj)*64 + 2*lane);
                #pragma unroll
                for (int e = 0; e < 8; e++) {
                    const float h = (jj==0)?hv[e].x:(jj==1)?hv[e].y:(jj==2)?hv[e].z:hv[e].w;
                    a2[e][0] = fmaf(h, w.x, a2[e][0]);
                    a2[e][1] = fmaf(h, w.y, a2[e][1]);
                }
            }
        }
        #pragma unroll
        for (int e = 0; e < 8; e++) {
            const int gi = base + rb + e;
            if (gi < N)
                *(float2*)(out + (size_t)gi*HD + 2*lane) = make_float2(a2[e][0], a2[e][1]);
        }
    }
}

// ---------------------------------------------------------------------------
extern "C" void kernel_launch(void* const* d_in, const int* in_sizes, int n_in,
                              void* d_out, int out_size)
{
    const float* h_v    = (const float*)d_in[0];
    const float* h_u    = (const float*)d_in[1];
    const float* e_feat = (const float*)d_in[2];
    const int*   ei     = (const int*)d_in[3];     // int32 edge_index [2, E]
    const int*   Sp     = (const int*)d_in[4];     // int32 scalar S
    const float* a2u_w1 = (const float*)d_in[5];
    const float* a2u_b1 = (const float*)d_in[6];
    const float* a2u_w2 = (const float*)d_in[7];
    const float* a2u_b2 = (const float*)d_in[8];
    const float* u_w1   = (const float*)d_in[9];
    const float* u_b1   = (const float*)d_in[10];
    const float* u_w2   = (const float*)d_in[11];
    const float* u_b2   = (const float*)d_in[12];
    const float* u2a_w1 = (const float*)d_in[13];
    const float* u2a_b1 = (const float*)d_in[14];
    const float* u2a_w2 = (const float*)d_in[15];
    const float* u2a_b2 = (const float*)d_in[16];
    const float* a_w1   = (const float*)d_in[17];
    const float* a_b1   = (const float*)d_in[18];
    const float* a_w2   = (const float*)d_in[19];
    const float* a_b2   = (const float*)d_in[20];

    const int NVn = in_sizes[0] / HD;
    const int NUn = in_sizes[1] / HD;
    const int E   = in_sizes[3] / 2;
    const int* src = ei;
    const int* dst = ei + E;

    float *m_u = nullptr, *m_v = nullptr, *degp = nullptr;
    cudaGetSymbolAddress((void**)&m_u, g_m_u);
    cudaGetSymbolAddress((void**)&m_v, g_m_v);
    cudaGetSymbolAddress((void**)&degp, g_deg);

    int sms = 148;
    cudaDeviceGetAttribute(&sms, cudaDevAttrMultiProcessorCount, 0);

    cudaFuncSetAttribute(edge_mlp_kernel,
                         cudaFuncAttributeMaxDynamicSharedMemorySize, EDGE_SMEM_BYTES);
    cudaFuncSetAttribute(node_mlp_kernel,
                         cudaFuncAttributeMaxDynamicSharedMemorySize, NODE_SMEM_BYTES);

    cudaMemsetAsync(m_u,  0, (size_t)NUn * HD * sizeof(float));
    cudaMemsetAsync(m_v,  0, (size_t)NVn * HD * sizeof(float));
    cudaMemsetAsync(degp, 0, (size_t)NVn * sizeof(float));

    float* h_v_out = (float*)d_out;
    float* h_u_out = (float*)d_out + (size_t)NVn * HD;

    // Pass 1: a -> u messages, scatter to m_u[dst]; count deg[src]
    edge_mlp_kernel<<<sms, TPB, EDGE_SMEM_BYTES>>>(
        h_v, src, h_u, dst, e_feat, dst,
        a2u_w1, a2u_b1, a2u_w2, a2u_b2, m_u, degp, E);

    // u node update: h_u_out = MLP([h_u, m_u / S])
    node_mlp_kernel<<<2 * sms, TPB, NODE_SMEM_BYTES>>>(
        h_u, m_u, nullptr, Sp,
        u_w1, u_b1, u_w2, u_b2, h_u_out, NUn);

    // Pass 2: u -> a messages, scatter to m_v[src]
    edge_mlp_kernel<<<sms, TPB, EDGE_SMEM_BYTES>>>(
        h_u_out, dst, h_v, src, e_feat, src,
        u2a_w1, u2a_b1, u2a_w2, u2a_b2, m_v, nullptr, E);

    // v node update: h_v_out = MLP([h_v, m_v / max(deg,1)])
    node_mlp_kernel<<<2 * sms, TPB, NODE_SMEM_BYTES>>>(
        h_v, m_v, degp, nullptr,
        a_w1, a_b1, a_w2, a_b2, h_v_out, NVn);
}

// round 5
// speedup vs baseline: 1.0181x; 1.0181x over previous
#include <cuda_runtime.h>

// ---------------------------------------------------------------------------
// SparseMPNNLayer: fused fp32 implementation, FFMA2 (fma.rn.f32x2) edge GEMMs.
//   pass1: msg = MLP([h_v[src], h_u[dst], e_feat]) -> atomic scatter to m_u[dst]
//          deg[src] += 1
//   node1: h_u_out = MLP([h_u, m_u/S])              (written to d_out+NV*64)
//   pass2: msg = MLP([h_u_out[dst], h_v[src], e_feat]) -> scatter to m_v[src]
//   node2: h_v_out = MLP([h_v, m_v/max(deg,1)])     (written to d_out)
// ---------------------------------------------------------------------------

#define ETPB 512
#define NTPB 256
constexpr int HD = 64;
constexpr int MAXN = 100000;

// Scratch (device globals: allowed; runtime alloc is not)
__device__ float g_m_u[(size_t)MAXN * HD];
__device__ float g_m_v[(size_t)MAXN * HD];
__device__ float g_deg[MAXN];

// Padded smem row strides (floats) to avoid bank conflicts on staging stores.
constexpr int XS = 196;   // 192 cols + 4 pad  (784B/row, 16B aligned)
constexpr int HS = 132;   // 128 cols + 4 pad  (528B/row, 16B aligned)

constexpr int EDGE_SMEM_FLOATS = 192*128 + 128*64 + 128 + 64 + 64*XS + 64*HS;
constexpr int NODE_SMEM_FLOATS = 128*64 + 64*64 + 64 + 64 + 64*128 + 64*64;
constexpr int EDGE_SMEM_BYTES = EDGE_SMEM_FLOATS * 4;   // 215808
constexpr int NODE_SMEM_BYTES = NODE_SMEM_FLOATS * 4;   // 98816

// ---- packed fp32x2 helpers (sm_103a FFMA2) --------------------------------
__device__ __forceinline__ unsigned long long ffma2(
    unsigned long long a, unsigned long long b, unsigned long long c) {
    unsigned long long d;
    asm("fma.rn.f32x2 %0, %1, %2, %3;" : "=l"(d) : "l"(a), "l"(b), "l"(c));
    return d;
}
__device__ __forceinline__ unsigned long long dup2(float x) {
    unsigned long long r;
    asm("mov.b64 %0, {%1, %1};" : "=l"(r) : "f"(x));
    return r;
}
__device__ __forceinline__ float2 unpk2(unsigned long long v) {
    float2 f;
    asm("mov.b64 {%0, %1}, %2;" : "=f"(f.x), "=f"(f.y) : "l"(v));
    return f;
}

// ---------------------------------------------------------------------------
// Edge MLP: x = [A[idxA[e]], B[idxB[e]], EF[e]] (192) -> relu(x@W1+b1) (128)
//           -> @W2+b2 (64) -> atomicAdd into accum[idxOut[e]]
// 512 threads, persistent, tile = 64 edges. Warp: 4 edges x 128 hid (GEMM1),
// 4 edges x 64 out (GEMM2). Inner loops use fma.rn.f32x2.
// ---------------------------------------------------------------------------
__global__ void __launch_bounds__(ETPB) edge_mlp_kernel(
    const float* __restrict__ A, const int* __restrict__ idxA,
    const float* __restrict__ B, const int* __restrict__ idxB,
    const float* __restrict__ EF,
    const int* __restrict__ idxOut,
    const float* __restrict__ W1, const float* __restrict__ b1,
    const float* __restrict__ W2, const float* __restrict__ b2,
    float* __restrict__ accum, float* __restrict__ deg,
    int E)
{
    extern __shared__ float sm[];
    float* sW1 = sm;                    // 192*128
    float* sW2 = sW1 + 192*128;         // 128*64
    float* sb1 = sW2 + 128*64;          // 128
    float* sb2 = sb1 + 128;             // 64
    float* sX  = sb2 + 64;              // 64*XS
    float* sH  = sX + 64*XS;            // 64*HS

    const int tid = threadIdx.x;
    for (int i = tid; i < (192*128)/4; i += ETPB)
        ((float4*)sW1)[i] = ((const float4*)W1)[i];
    for (int i = tid; i < (128*64)/4; i += ETPB)
        ((float4*)sW2)[i] = ((const float4*)W2)[i];
    if (tid < 128) sb1[tid] = b1[tid];
    if (tid < 64)  sb2[tid] = b2[tid];

    const int warp = tid >> 5, lane = tid & 31;
    const int sel = tid >> 3, sq = tid & 7;   // staging: 64 edges x 8 threads
    const int ntiles = (E + 63) >> 6;

    for (int tile = blockIdx.x; tile < ntiles; tile += gridDim.x) {
        const int base = tile << 6;
        __syncthreads();  // smem reuse barrier (also covers weight staging)

        // ---- stage X tile [64][192] (row stride XS) ----
        {
            const int e = base + sel;
            if (e < E) {
                const float4* ra = (const float4*)(A  + (size_t)idxA[e] * HD);
                const float4* rb = (const float4*)(B  + (size_t)idxB[e] * HD);
                const float4* re = (const float4*)(EF + (size_t)e * HD);
                float4* xr = (float4*)(sX + sel * XS);
                xr[sq]      = ra[sq];
                xr[8 + sq]  = ra[8 + sq];
                xr[16 + sq] = rb[sq];
                xr[24 + sq] = rb[8 + sq];
                xr[32 + sq] = re[sq];
                xr[40 + sq] = re[8 + sq];
            }
        }
        __syncthreads();

        // ---- GEMM1: warp does 4 edges x 128 hidden; lane owns 4*lane..+3 ----
        const int eb = warp * 4;
        unsigned long long acc[4][2];
        {
            const ulonglong2 bb = *(const ulonglong2*)(sb1 + 4*lane);
            #pragma unroll
            for (int e = 0; e < 4; e++) { acc[e][0] = bb.x; acc[e][1] = bb.y; }
        }
        #pragma unroll 1
        for (int k = 0; k < 192; k += 4) {
            float4 xv[4];
            #pragma unroll
            for (int e = 0; e < 4; e++)
                xv[e] = *(const float4*)(sX + (eb + e)*XS + k);  // broadcast
            #pragma unroll
            for (int kk = 0; kk < 4; kk++) {
                const ulonglong2 wv = *(const ulonglong2*)(sW1 + (k + kk)*128 + 4*lane);
                #pragma unroll
                for (int e = 0; e < 4; e++) {
                    const float x = (kk==0)?xv[e].x:(kk==1)?xv[e].y:(kk==2)?xv[e].z:xv[e].w;
                    const unsigned long long xx = dup2(x);
                    acc[e][0] = ffma2(xx, wv.x, acc[e][0]);
                    acc[e][1] = ffma2(xx, wv.y, acc[e][1]);
                }
            }
        }
        #pragma unroll
        for (int e = 0; e < 4; e++) {
            const float2 h01 = unpk2(acc[e][0]);
            const float2 h23 = unpk2(acc[e][1]);
            float4 h = make_float4(fmaxf(h01.x, 0.f), fmaxf(h01.y, 0.f),
                                   fmaxf(h23.x, 0.f), fmaxf(h23.y, 0.f));
            *(float4*)(sH + (eb + e)*HS + 4*lane) = h;
        }
        __syncthreads();

        // ---- GEMM2: warp does 4 edges x 64 out; lane owns 2*lane..+1 ----
        unsigned long long a2[4];
        {
            const unsigned long long bb = *(const unsigned long long*)(sb2 + 2*lane);
            #pragma unroll
            for (int e = 0; e < 4; e++) a2[e] = bb;
        }
        #pragma unroll 1
        for (int j = 0; j < 128; j += 4) {
            float4 hv[4];
            #pragma unroll
            for (int e = 0; e < 4; e++)
                hv[e] = *(const float4*)(sH + (eb + e)*HS + j);  // broadcast
            #pragma unroll
            for (int jj = 0; jj < 4; jj++) {
                const unsigned long long w =
                    *(const unsigned long long*)(sW2 + (j + jj)*64 + 2*lane);
                #pragma unroll
                for (int e = 0; e < 4; e++) {
                    const float h = (jj==0)?hv[e].x:(jj==1)?hv[e].y:(jj==2)?hv[e].z:hv[e].w;
                    a2[e] = ffma2(dup2(h), w, a2[e]);
                }
            }
        }

        // ---- scatter ----
        #pragma unroll
        for (int e = 0; e < 4; e++) {
            const int ge = base + eb + e;
            if (ge < E) {
                const int d = idxOut[ge];
                const float2 v = unpk2(a2[e]);
                atomicAdd(accum + (size_t)d*HD + 2*lane,     v.x);
                atomicAdd(accum + (size_t)d*HD + 2*lane + 1, v.y);
            }
        }
        if (deg != nullptr && warp < 2) {
            const int ge = base + warp*32 + lane;
            if (ge < E) atomicAdd(deg + idxA[ge], 1.0f);
        }
    }
}

// ---------------------------------------------------------------------------
// Node MLP: x = [self[i], msum[i]*scale] (128) -> relu(x@W1+b1) (64) -> @W2+b2
//   scale = 1/S (Sp != null) or 1/max(deg[i],1)
// ---------------------------------------------------------------------------
__global__ void __launch_bounds__(NTPB) node_mlp_kernel(
    const float* __restrict__ selfF, const float* __restrict__ msum,
    const float* __restrict__ deg, const int* __restrict__ Sp,
    const float* __restrict__ W1, const float* __restrict__ b1,
    const float* __restrict__ W2, const float* __restrict__ b2,
    float* __restrict__ out, int N)
{
    extern __shared__ float sm[];
    float* sW1 = sm;            // 128*64
    float* sW2 = sW1 + 128*64;  // 64*64
    float* sb1 = sW2 + 64*64;   // 64
    float* sb2 = sb1 + 64;      // 64
    float* sX  = sb2 + 64;      // 64*128
    float* sH  = sX + 64*128;   // 64*64

    const int tid = threadIdx.x;
    for (int i = tid; i < (128*64)/4; i += NTPB)
        ((float4*)sW1)[i] = ((const float4*)W1)[i];
    for (int i = tid; i < (64*64)/4; i += NTPB)
        ((float4*)sW2)[i] = ((const float4*)W2)[i];
    if (tid < 64) { sb1[tid] = b1[tid]; sb2[tid] = b2[tid]; }

    const float invS = (Sp != nullptr) ? (1.0f / (float)(*Sp)) : 0.0f;

    const int warp = tid >> 5, lane = tid & 31;
    const int ntiles = (N + 63) >> 6;

    for (int tile = blockIdx.x; tile < ntiles; tile += gridDim.x) {
        const int base = tile << 6;
        __syncthreads();

        // ---- stage X tile [64][128] ----
        {
            const int r = tid >> 2, q = tid & 3;
            const int i = base + r;
            if (i < N) {
                const float sc = (Sp != nullptr) ? invS : (1.0f / fmaxf(deg[i], 1.0f));
                const float4* rs = (const float4*)(selfF + (size_t)i * HD) + q*4;
                const float4* rm = (const float4*)(msum  + (size_t)i * HD) + q*4;
                float4* xr = (float4*)(sX + r * 128);
                #pragma unroll
                for (int t = 0; t < 4; t++) xr[q*4 + t] = rs[t];
                #pragma unroll
                for (int t = 0; t < 4; t++) {
                    float4 v = rm[t];
                    v.x *= sc; v.y *= sc; v.z *= sc; v.w *= sc;
                    xr[16 + q*4 + t] = v;
                }
            }
        }
        __syncthreads();

        const int rb = warp * 8;
        float acc[8][2];
        {
            const float2 bv = *(const float2*)(sb1 + 2*lane);
            #pragma unroll
            for (int e = 0; e < 8; e++) { acc[e][0]=bv.x; acc[e][1]=bv.y; }
        }
        #pragma unroll 1
        for (int k = 0; k < 128; k += 4) {
            float4 xv[8];
            #pragma unroll
            for (int e = 0; e < 8; e++)
                xv[e] = *(const float4*)(sX + (rb + e)*128 + k);
            #pragma unroll
            for (int kk = 0; kk < 4; kk++) {
                const float2 w = *(const float2*)(sW1 + (k + kk)*64 + 2*lane);
                #pragma unroll
                for (int e = 0; e < 8; e++) {
                    const float x = (kk==0)?xv[e].x:(kk==1)?xv[e].y:(kk==2)?xv[e].z:xv[e].w;
                    acc[e][0] = fmaf(x, w.x, acc[e][0]);
                    acc[e][1] = fmaf(x, w.y, acc[e][1]);
                }
            }
        }
        #pragma unroll
        for (int e = 0; e < 8; e++) {
            float2 h = make_float2(fmaxf(acc[e][0], 0.f), fmaxf(acc[e][1], 0.f));
            *(float2*)(sH + (rb + e)*64 + 2*lane) = h;
        }
        __syncthreads();

        float a2[8][2];
        {
            const float2 bv = *(const float2*)(sb2 + 2*lane);
            #pragma unroll
            for (int e = 0; e < 8; e++) { a2[e][0]=bv.x; a2[e][1]=bv.y; }
        }
        #pragma unroll 1
        for (int j = 0; j < 64; j += 4) {
            float4 hv[8];
            #pragma unroll
            for (int e = 0; e < 8; e++)
                hv[e] = *(const float4*)(sH + (rb + e)*64 + j);
            #pragma unroll
            for (int jj = 0; jj < 4; jj++) {
                const float2 w = *(const float2*)(sW2 + (j + jj)*64 + 2*lane);
                #pragma unroll
                for (int e = 0; e < 8; e++) {
                    const float h = (jj==0)?hv[e].x:(jj==1)?hv[e].y:(jj==2)?hv[e].z:hv[e].w;
                    a2[e][0] = fmaf(h, w.x, a2[e][0]);
                    a2[e][1] = fmaf(h, w.y, a2[e][1]);
                }
            }
        }
        #pragma unroll
        for (int e = 0; e < 8; e++) {
            const int gi = base + rb + e;
            if (gi < N)
                *(float2*)(out + (size_t)gi*HD + 2*lane) = make_float2(a2[e][0], a2[e][1]);
        }
    }
}

// ---------------------------------------------------------------------------
extern "C" void kernel_launch(void* const* d_in, const int* in_sizes, int n_in,
                              void* d_out, int out_size)
{
    const float* h_v    = (const float*)d_in[0];
    const float* h_u    = (const float*)d_in[1];
    const float* e_feat = (const float*)d_in[2];
    const int*   ei     = (const int*)d_in[3];     // int32 edge_index [2, E]
    const int*   Sp     = (const int*)d_in[4];     // int32 scalar S
    const float* a2u_w1 = (const float*)d_in[5];
    const float* a2u_b1 = (const float*)d_in[6];
    const float* a2u_w2 = (const float*)d_in[7];
    const float* a2u_b2 = (const float*)d_in[8];
    const float* u_w1   = (const float*)d_in[9];
    const float* u_b1   = (const float*)d_in[10];
    const float* u_w2   = (const float*)d_in[11];
    const float* u_b2   = (const float*)d_in[12];
    const float* u2a_w1 = (const float*)d_in[13];
    const float* u2a_b1 = (const float*)d_in[14];
    const float* u2a_w2 = (const float*)d_in[15];
    const float* u2a_b2 = (const float*)d_in[16];
    const float* a_w1   = (const float*)d_in[17];
    const float* a_b1   = (const float*)d_in[18];
    const float* a_w2   = (const float*)d_in[19];
    const float* a_b2   = (const float*)d_in[20];

    const int NVn = in_sizes[0] / HD;
    const int NUn = in_sizes[1] / HD;
    const int E   = in_sizes[3] / 2;
    const int* src = ei;
    const int* dst = ei + E;

    float *m_u = nullptr, *m_v = nullptr, *degp = nullptr;
    cudaGetSymbolAddress((void**)&m_u, g_m_u);
    cudaGetSymbolAddress((void**)&m_v, g_m_v);
    cudaGetSymbolAddress((void**)&degp, g_deg);

    int sms = 148;
    cudaDeviceGetAttribute(&sms, cudaDevAttrMultiProcessorCount, 0);

    cudaFuncSetAttribute(edge_mlp_kernel,
                         cudaFuncAttributeMaxDynamicSharedMemorySize, EDGE_SMEM_BYTES);
    cudaFuncSetAttribute(node_mlp_kernel,
                         cudaFuncAttributeMaxDynamicSharedMemorySize, NODE_SMEM_BYTES);

    cudaMemsetAsync(m_u,  0, (size_t)NUn * HD * sizeof(float));
    cudaMemsetAsync(m_v,  0, (size_t)NVn * HD * sizeof(float));
    cudaMemsetAsync(degp, 0, (size_t)NVn * sizeof(float));

    float* h_v_out = (float*)d_out;
    float* h_u_out = (float*)d_out + (size_t)NVn * HD;

    // Pass 1: a -> u messages, scatter to m_u[dst]; count deg[src]
    edge_mlp_kernel<<<sms, ETPB, EDGE_SMEM_BYTES>>>(
        h_v, src, h_u, dst, e_feat, dst,
        a2u_w1, a2u_b1, a2u_w2, a2u_b2, m_u, degp, E);

    // u node update: h_u_out = MLP([h_u, m_u / S])
    node_mlp_kernel<<<2 * sms, NTPB, NODE_SMEM_BYTES>>>(
        h_u, m_u, nullptr, Sp,
        u_w1, u_b1, u_w2, u_b2, h_u_out, NUn);

    // Pass 2: u -> a messages, scatter to m_v[src]
    edge_mlp_kernel<<<sms, ETPB, EDGE_SMEM_BYTES>>>(
        h_u_out, dst, h_v, src, e_feat, src,
        u2a_w1, u2a_b1, u2a_w2, u2a_b2, m_v, nullptr, E);

    // v node update: h_v_out = MLP([h_v, m_v / max(deg,1)])
    node_mlp_kernel<<<2 * sms, NTPB, NODE_SMEM_BYTES>>>(
        h_v, m_v, degp, nullptr,
        a_w1, a_b1, a_w2, a_b2, h_v_out, NVn);
}

// round 7
// speedup vs baseline: 2.3363x; 2.2948x over previous
#include <cuda_runtime.h>
#include <cstdint>

// ---------------------------------------------------------------------------
// SparseMPNNLayer — edge MLPs via mma.sync tf32 (base sm_103 target), node
// MLPs on CUDA cores.
//   pass1: msg = MLP([h_v[src], h_u[dst], e_feat]) -> atomic scatter m_u[dst]
//          deg[src] += 1
//   node1: h_u_out = MLP([h_u, m_u/S])
//   pass2: msg = MLP([h_u_out[dst], h_v[src], e_feat]) -> scatter m_v[src]
//   node2: h_v_out = MLP([h_v, m_v/max(deg,1)])
// ---------------------------------------------------------------------------

#define NTPB 256
#define ETPB 256
constexpr int HD = 64;
constexpr int MAXN = 100000;

__device__ float g_m_u[(size_t)MAXN * HD];
__device__ float g_m_v[(size_t)MAXN * HD];
__device__ float g_deg[MAXN];

// ---- smem layout (in 4-byte words) ----------------------------------------
constexpr int W1T_OFF = 0;                    // [128 n][192 k] tf32
constexpr int W2T_OFF = W1T_OFF + 128 * 192;  // [64 n][128 k] tf32
constexpr int X_OFF   = W2T_OFF + 64 * 128;   // [128 e][192 k] tf32 (H aliases)
constexpr int B1_OFF  = X_OFF + 128 * 192;    // 128 f32
constexpr int B2_OFF  = B1_OFF + 128;         // 64 f32
constexpr int EDGE_SMEM_WORDS = B2_OFF + 64;
constexpr int EDGE_SMEM = EDGE_SMEM_WORDS * 4;   // 230144 B

__device__ __forceinline__ uint32_t f2tf(float f) {
    uint32_t r;
    asm("cvt.rna.tf32.f32 %0, %1;" : "=r"(r) : "f"(f));
    return r;
}

__device__ __forceinline__ void mma8(float* c, uint32_t a0, uint32_t a1,
                                     uint32_t a2, uint32_t a3,
                                     uint32_t b0, uint32_t b1) {
    asm("mma.sync.aligned.m16n8k8.row.col.f32.tf32.tf32.f32 "
        "{%0,%1,%2,%3}, {%4,%5,%6,%7}, {%8,%9}, {%0,%1,%2,%3};"
        : "+f"(c[0]), "+f"(c[1]), "+f"(c[2]), "+f"(c[3])
        : "r"(a0), "r"(a1), "r"(a2), "r"(a3), "r"(b0), "r"(b1));
}

// XOR-swizzled chunk store: row-stride in words, chunk = 16B unit index.
__device__ __forceinline__ void st_chunk(uint32_t* b, int row, int stride,
                                         int chunk, uint4 v) {
    const int c = (chunk & ~7) | ((chunk & 7) ^ (row & 7));
    *(uint4*)(b + row * stride + c * 4) = v;
}
__device__ __forceinline__ uint4 cvt4(float4 v) {
    uint4 r;
    r.x = f2tf(v.x); r.y = f2tf(v.y); r.z = f2tf(v.z); r.w = f2tf(v.w);
    return r;
}

// ---------------------------------------------------------------------------
// Edge MLP (mma.sync tf32):
//   x = [A[idxA[e]] | B[idxB[e]] | EF[e]] (192) -> relu(x@W1+b1) (128)
//     -> @W2+b2 (64) -> atomicAdd accum[idxOut[e]]
// Tile = 128 edges, 8 warps. GEMM1 warp: 32e x 64h. GEMM2 warp: 32e x 32o.
// ---------------------------------------------------------------------------
__global__ void __launch_bounds__(ETPB, 1) edge_mlp_tc(
    const float* __restrict__ A, const int* __restrict__ idxA,
    const float* __restrict__ B, const int* __restrict__ idxB,
    const float* __restrict__ EF, const int* __restrict__ idxOut,
    const float* __restrict__ W1, const float* __restrict__ b1,
    const float* __restrict__ W2, const float* __restrict__ b2,
    float* __restrict__ accum, float* __restrict__ deg, int E)
{
    extern __shared__ uint32_t smu[];
    uint32_t* W1s = smu + W1T_OFF;
    uint32_t* W2s = smu + W2T_OFF;
    uint32_t* Xs  = smu + X_OFF;
    uint32_t* Hs  = smu + X_OFF;           // aliases X (X dead after GEMM1)
    float* sB1 = (float*)(smu + B1_OFF);
    float* sB2 = (float*)(smu + B2_OFF);

    const int tid = threadIdx.x;
    const int warp = tid >> 5, lane = tid & 31;
    const int g = lane >> 2, t = lane & 3;   // mma groupID / threadID-in-group

    // ---- one-time: weights transposed + tf32 + swizzled -------------------
    for (int i = tid; i < 128 * 192; i += ETPB) {
        const int n = i & 127, k = i >> 7;                 // coalesced gmem
        const int ch = k >> 2;
        const int cc = (ch & ~7) | ((ch & 7) ^ (n & 7));
        W1s[n * 192 + cc * 4 + (k & 3)] = f2tf(W1[k * 128 + n]);
    }
    for (int i = tid; i < 64 * 128; i += ETPB) {
        const int n = i & 63, k = i >> 6;
        const int ch = k >> 2;
        const int cc = (ch & ~7) | ((ch & 7) ^ (n & 7));
        W2s[n * 128 + cc * 4 + (k & 3)] = f2tf(W2[k * 64 + n]);
    }
    if (tid < 128) sB1[tid] = b1[tid];
    if (tid < 64)  sB2[tid] = b2[tid];
    __syncthreads();

    // per-thread swizzle offsets: addr = rowbase + ((C&~7)<<2) + off3[C&7]
    int off3[8];
    #pragma unroll
    for (int c = 0; c < 8; c++) off3[c] = ((c ^ g) << 2) + t;

    const int m0 = (warp >> 1) * 32;         // edge rows of this warp
    const int n0 = (warp & 1) * 64;          // GEMM1 hidden cols
    const int nb = (warp & 1) * 32;          // GEMM2 out cols

    int arA[2][2], arH[2][2], brB[8], br2[4];
    #pragma unroll
    for (int mi = 0; mi < 2; mi++) {
        arA[mi][0] = (m0 + mi * 16 + g) * 192;
        arA[mi][1] = (m0 + mi * 16 + g + 8) * 192;
        arH[mi][0] = (m0 + mi * 16 + g) * 128;
        arH[mi][1] = (m0 + mi * 16 + g + 8) * 128;
    }
    #pragma unroll
    for (int ni = 0; ni < 8; ni++) brB[ni] = (n0 + ni * 8 + g) * 192;
    #pragma unroll
    for (int ni = 0; ni < 4; ni++) br2[ni] = (nb + ni * 8 + g) * 128;

    const int el = tid >> 1, half = tid & 1;   // staging roles
    const int ntiles = (E + 127) >> 7;

    for (int tile = blockIdx.x; tile < ntiles; tile += gridDim.x) {
        const int base = tile << 7;

        // ---- stage X [128][192] gathered, tf32, swizzled ----
        {
            const int ge = base + el;
            if (ge < E) {
                if (half == 0) {
                    const float4* s = (const float4*)(A + (size_t)idxA[ge] * HD);
                    #pragma unroll
                    for (int j = 0; j < 16; j++)
                        st_chunk(Xs, el, 192, j, cvt4(s[j]));
                    const float4* e4 = (const float4*)(EF + (size_t)ge * HD);
                    #pragma unroll
                    for (int j = 0; j < 8; j++)
                        st_chunk(Xs, el, 192, 32 + j, cvt4(e4[j]));
                } else {
                    const float4* s = (const float4*)(B + (size_t)idxB[ge] * HD);
                    #pragma unroll
                    for (int j = 0; j < 16; j++)
                        st_chunk(Xs, el, 192, 16 + j, cvt4(s[j]));
                    const float4* e4 = (const float4*)(EF + (size_t)ge * HD);
                    #pragma unroll
                    for (int j = 0; j < 8; j++)
                        st_chunk(Xs, el, 192, 40 + j, cvt4(e4[8 + j]));
                }
            }
        }
        __syncthreads();   // X ready

        // ---- GEMM1: 32e x 64h, K=192 ----
        float c1[2][8][4];
        #pragma unroll
        for (int mi = 0; mi < 2; mi++)
            #pragma unroll
            for (int ni = 0; ni < 8; ni++)
                #pragma unroll
                for (int q = 0; q < 4; q++) c1[mi][ni][q] = 0.0f;

        #pragma unroll
        for (int ks = 0; ks < 24; ks++) {
            const int C0 = 2 * ks, C1 = 2 * ks + 1;
            const int o0 = ((C0 & ~7) << 2) + off3[C0 & 7];
            const int o1 = ((C1 & ~7) << 2) + off3[C1 & 7];
            uint32_t a[2][4];
            #pragma unroll
            for (int mi = 0; mi < 2; mi++) {
                a[mi][0] = Xs[arA[mi][0] + o0];
                a[mi][1] = Xs[arA[mi][1] + o0];
                a[mi][2] = Xs[arA[mi][0] + o1];
                a[mi][3] = Xs[arA[mi][1] + o1];
            }
            uint32_t b[8][2];
            #pragma unroll
            for (int ni = 0; ni < 8; ni++) {
                b[ni][0] = W1s[brB[ni] + o0];
                b[ni][1] = W1s[brB[ni] + o1];
            }
            #pragma unroll
            for (int mi = 0; mi < 2; mi++)
                #pragma unroll
                for (int ni = 0; ni < 8; ni++)
                    mma8(c1[mi][ni], a[mi][0], a[mi][1], a[mi][2], a[mi][3],
                         b[ni][0], b[ni][1]);
        }
        __syncthreads();   // all X reads done (H aliases X)

        // ---- epilogue 1: relu(c1 + b1) -> H (tf32, swizzled) ----
        #pragma unroll
        for (int mi = 0; mi < 2; mi++) {
            const int r0 = m0 + mi * 16 + g;
            #pragma unroll
            for (int ni = 0; ni < 8; ni++) {
                const int col = n0 + ni * 8 + 2 * t;
                const float2 bb = *(const float2*)(sB1 + col);
                const int ch = col >> 2;
                const int cc = (ch & ~7) | ((ch & 7) ^ g);
                const int wo = cc * 4 + (col & 3);
                uint2 p;
                p.x = f2tf(fmaxf(c1[mi][ni][0] + bb.x, 0.0f));
                p.y = f2tf(fmaxf(c1[mi][ni][1] + bb.y, 0.0f));
                *(uint2*)(Hs + r0 * 128 + wo) = p;
                p.x = f2tf(fmaxf(c1[mi][ni][2] + bb.x, 0.0f));
                p.y = f2tf(fmaxf(c1[mi][ni][3] + bb.y, 0.0f));
                *(uint2*)(Hs + (r0 + 8) * 128 + wo) = p;
            }
        }
        if (deg != nullptr && tid < 128) {
            const int ge = base + tid;
            if (ge < E) atomicAdd(deg + idxA[ge], 1.0f);
        }
        __syncthreads();   // H ready

        // ---- GEMM2: 32e x 32o, K=128 ----
        float c2[2][4][4];
        #pragma unroll
        for (int mi = 0; mi < 2; mi++)
            #pragma unroll
            for (int ni = 0; ni < 4; ni++)
                #pragma unroll
                for (int q = 0; q < 4; q++) c2[mi][ni][q] = 0.0f;

        #pragma unroll
        for (int ks = 0; ks < 16; ks++) {
            const int C0 = 2 * ks, C1 = 2 * ks + 1;
            const int o0 = ((C0 & ~7) << 2) + off3[C0 & 7];
            const int o1 = ((C1 & ~7) << 2) + off3[C1 & 7];
            uint32_t a[2][4];
            #pragma unroll
            for (int mi = 0; mi < 2; mi++) {
                a[mi][0] = Hs[arH[mi][0] + o0];
                a[mi][1] = Hs[arH[mi][1] + o0];
                a[mi][2] = Hs[arH[mi][0] + o1];
                a[mi][3] = Hs[arH[mi][1] + o1];
            }
            uint32_t b[4][2];
            #pragma unroll
            for (int ni = 0; ni < 4; ni++) {
                b[ni][0] = W2s[br2[ni] + o0];
                b[ni][1] = W2s[br2[ni] + o1];
            }
            #pragma unroll
            for (int mi = 0; mi < 2; mi++)
                #pragma unroll
                for (int ni = 0; ni < 4; ni++)
                    mma8(c2[mi][ni], a[mi][0], a[mi][1], a[mi][2], a[mi][3],
                         b[ni][0], b[ni][1]);
        }

        // ---- epilogue 2: + b2, atomic scatter ----
        #pragma unroll
        for (int mi = 0; mi < 2; mi++) {
            const int r0 = m0 + mi * 16 + g;
            const int ge0 = base + r0, ge1 = ge0 + 8;
            const int d0 = (ge0 < E) ? idxOut[ge0] : -1;
            const int d1 = (ge1 < E) ? idxOut[ge1] : -1;
            #pragma unroll
            for (int ni = 0; ni < 4; ni++) {
                const int col = nb + ni * 8 + 2 * t;
                const float2 bb = *(const float2*)(sB2 + col);
                if (d0 >= 0) {
                    float* p = accum + (size_t)d0 * HD + col;
                    atomicAdd(p,     c2[mi][ni][0] + bb.x);
                    atomicAdd(p + 1, c2[mi][ni][1] + bb.y);
                }
                if (d1 >= 0) {
                    float* p = accum + (size_t)d1 * HD + col;
                    atomicAdd(p,     c2[mi][ni][2] + bb.x);
                    atomicAdd(p + 1, c2[mi][ni][3] + bb.y);
                }
            }
        }
        __syncthreads();   // H reads done before next tile's X staging
    }
}

// ---------------------------------------------------------------------------
// Node MLP (fp32): x=[self, msum*scale](128)->relu(@W1+b1)(64)->@W2+b2
// ---------------------------------------------------------------------------
constexpr int NODE_SMEM_FLOATS = 128*64 + 64*64 + 64 + 64 + 64*128 + 64*64;
constexpr int NODE_SMEM_BYTES = NODE_SMEM_FLOATS * 4;

__global__ void __launch_bounds__(NTPB) node_mlp_kernel(
    const float* __restrict__ selfF, const float* __restrict__ msum,
    const float* __restrict__ deg, const int* __restrict__ Sp,
    const float* __restrict__ W1, const float* __restrict__ b1,
    const float* __restrict__ W2, const float* __restrict__ b2,
    float* __restrict__ out, int N)
{
    extern __shared__ float sm[];
    float* sW1 = sm;            // 128*64
    float* sW2 = sW1 + 128*64;  // 64*64
    float* sb1 = sW2 + 64*64;   // 64
    float* sb2 = sb1 + 64;      // 64
    float* sX  = sb2 + 64;      // 64*128
    float* sH  = sX + 64*128;   // 64*64

    const int tid = threadIdx.x;
    for (int i = tid; i < (128*64)/4; i += NTPB)
        ((float4*)sW1)[i] = ((const float4*)W1)[i];
    for (int i = tid; i < (64*64)/4; i += NTPB)
        ((float4*)sW2)[i] = ((const float4*)W2)[i];
    if (tid < 64) { sb1[tid] = b1[tid]; sb2[tid] = b2[tid]; }

    const float invS = (Sp != nullptr) ? (1.0f / (float)(*Sp)) : 0.0f;
    const int warp = tid >> 5, lane = tid & 31;
    const int ntiles = (N + 63) >> 6;

    for (int tile = blockIdx.x; tile < ntiles; tile += gridDim.x) {
        const int base = tile << 6;
        __syncthreads();
        {
            const int r = tid >> 2, q = tid & 3;
            const int i = base + r;
            if (i < N) {
                const float sc = (Sp != nullptr) ? invS : (1.0f / fmaxf(deg[i], 1.0f));
                const float4* rs = (const float4*)(selfF + (size_t)i * HD) + q*4;
                const float4* rm = (const float4*)(msum  + (size_t)i * HD) + q*4;
                float4* xr = (float4*)(sX + r * 128);
                #pragma unroll
                for (int tt = 0; tt < 4; tt++) xr[q*4 + tt] = rs[tt];
                #pragma unroll
                for (int tt = 0; tt < 4; tt++) {
                    float4 v = rm[tt];
                    v.x *= sc; v.y *= sc; v.z *= sc; v.w *= sc;
                    xr[16 + q*4 + tt] = v;
                }
            }
        }
        __syncthreads();

        const int rb = warp * 8;
        float acc[8][2];
        {
            const float2 bv = *(const float2*)(sb1 + 2*lane);
            #pragma unroll
            for (int e = 0; e < 8; e++) { acc[e][0]=bv.x; acc[e][1]=bv.y; }
        }
        #pragma unroll 1
        for (int k = 0; k < 128; k += 4) {
            float4 xv[8];
            #pragma unroll
            for (int e = 0; e < 8; e++)
                xv[e] = *(const float4*)(sX + (rb + e)*128 + k);
            #pragma unroll
            for (int kk = 0; kk < 4; kk++) {
                const float2 w = *(const float2*)(sW1 + (k + kk)*64 + 2*lane);
                #pragma unroll
                for (int e = 0; e < 8; e++) {
                    const float x = (kk==0)?xv[e].x:(kk==1)?xv[e].y:(kk==2)?xv[e].z:xv[e].w;
                    acc[e][0] = fmaf(x, w.x, acc[e][0]);
                    acc[e][1] = fmaf(x, w.y, acc[e][1]);
                }
            }
        }
        #pragma unroll
        for (int e = 0; e < 8; e++) {
            float2 h = make_float2(fmaxf(acc[e][0], 0.f), fmaxf(acc[e][1], 0.f));
            *(float2*)(sH + (rb + e)*64 + 2*lane) = h;
        }
        __syncthreads();

        float a2[8][2];
        {
            const float2 bv = *(const float2*)(sb2 + 2*lane);
            #pragma unroll
            for (int e = 0; e < 8; e++) { a2[e][0]=bv.x; a2[e][1]=bv.y; }
        }
        #pragma unroll 1
        for (int j = 0; j < 64; j += 4) {
            float4 hv[8];
            #pragma unroll
            for (int e = 0; e < 8; e++)
                hv[e] = *(const float4*)(sH + (rb + e)*64 + j);
            #pragma unroll
            for (int jj = 0; jj < 4; jj++) {
                const float2 w = *(const float2*)(sW2 + (j + jj)*64 + 2*lane);
                #pragma unroll
                for (int e = 0; e < 8; e++) {
                    const float h = (jj==0)?hv[e].x:(jj==1)?hv[e].y:(jj==2)?hv[e].z:hv[e].w;
                    a2[e][0] = fmaf(h, w.x, a2[e][0]);
                    a2[e][1] = fmaf(h, w.y, a2[e][1]);
                }
            }
        }
        #pragma unroll
        for (int e = 0; e < 8; e++) {
            const int gi = base + rb + e;
            if (gi < N)
                *(float2*)(out + (size_t)gi*HD + 2*lane) = make_float2(a2[e][0], a2[e][1]);
        }
    }
}

// ---------------------------------------------------------------------------
extern "C" void kernel_launch(void* const* d_in, const int* in_sizes, int n_in,
                              void* d_out, int out_size)
{
    const float* h_v    = (const float*)d_in[0];
    const float* h_u    = (const float*)d_in[1];
    const float* e_feat = (const float*)d_in[2];
    const int*   ei     = (const int*)d_in[3];
    const int*   Sp     = (const int*)d_in[4];
    const float* a2u_w1 = (const float*)d_in[5];
    const float* a2u_b1 = (const float*)d_in[6];
    const float* a2u_w2 = (const float*)d_in[7];
    const float* a2u_b2 = (const float*)d_in[8];
    const float* u_w1   = (const float*)d_in[9];
    const float* u_b1   = (const float*)d_in[10];
    const float* u_w2   = (const float*)d_in[11];
    const float* u_b2   = (const float*)d_in[12];
    const float* u2a_w1 = (const float*)d_in[13];
    const float* u2a_b1 = (const float*)d_in[14];
    const float* u2a_w2 = (const float*)d_in[15];
    const float* u2a_b2 = (const float*)d_in[16];
    const float* a_w1   = (const float*)d_in[17];
    const float* a_b1   = (const float*)d_in[18];
    const float* a_w2   = (const float*)d_in[19];
    const float* a_b2   = (const float*)d_in[20];

    const int NVn = in_sizes[0] / HD;
    const int NUn = in_sizes[1] / HD;
    const int E   = in_sizes[3] / 2;
    const int* src = ei;
    const int* dst = ei + E;

    float *m_u = nullptr, *m_v = nullptr, *degp = nullptr;
    cudaGetSymbolAddress((void**)&m_u, g_m_u);
    cudaGetSymbolAddress((void**)&m_v, g_m_v);
    cudaGetSymbolAddress((void**)&degp, g_deg);

    int sms = 148;
    cudaDeviceGetAttribute(&sms, cudaDevAttrMultiProcessorCount, 0);

    cudaFuncSetAttribute(edge_mlp_tc,
                         cudaFuncAttributeMaxDynamicSharedMemorySize, EDGE_SMEM);
    cudaFuncSetAttribute(node_mlp_kernel,
                         cudaFuncAttributeMaxDynamicSharedMemorySize, NODE_SMEM_BYTES);

    cudaMemsetAsync(m_u,  0, (size_t)NUn * HD * sizeof(float));
    cudaMemsetAsync(m_v,  0, (size_t)NVn * HD * sizeof(float));
    cudaMemsetAsync(degp, 0, (size_t)NVn * sizeof(float));

    float* h_v_out = (float*)d_out;
    float* h_u_out = (float*)d_out + (size_t)NVn * HD;

    const int ntiles = (E + 127) >> 7;
    const int egrid = ntiles < sms ? ntiles : sms;

    // Pass 1: a -> u messages, scatter to m_u[dst]; count deg[src]
    edge_mlp_tc<<<egrid, ETPB, EDGE_SMEM>>>(
        h_v, src, h_u, dst, e_feat, dst,
        a2u_w1, a2u_b1, a2u_w2, a2u_b2, m_u, degp, E);

    // u node update
    node_mlp_kernel<<<2 * sms, NTPB, NODE_SMEM_BYTES>>>(
        h_u, m_u, nullptr, Sp,
        u_w1, u_b1, u_w2, u_b2, h_u_out, NUn);

    // Pass 2: u -> a messages, scatter to m_v[src]
    edge_mlp_tc<<<egrid, ETPB, EDGE_SMEM>>>(
        h_u_out, dst, h_v, src, e_feat, src,
        u2a_w1, u2a_b1, u2a_w2, u2a_b2, m_v, nullptr, E);

    // v node update
    node_mlp_kernel<<<2 * sms, NTPB, NODE_SMEM_BYTES>>>(
        h_v, m_v, degp, nullptr,
        a_w1, a_b1, a_w2, a_b2, h_v_out, NVn);
}

// round 8
// speedup vs baseline: 2.5184x; 1.0779x over previous
#include <cuda_runtime.h>
#include <cstdint>

// ---------------------------------------------------------------------------
// SparseMPNNLayer — edge AND node MLPs via mma.sync tf32 (base sm_103).
//   pass1: msg = MLP([h_v[src], h_u[dst], e_feat]) -> atomic scatter m_u[dst]
//          deg[src] += 1
//   node1: h_u_out = MLP([h_u, m_u/S])
//   pass2: msg = MLP([h_u_out[dst], h_v[src], e_feat]) -> scatter m_v[src]
//   node2: h_v_out = MLP([h_v, m_v/max(deg,1)])
// ---------------------------------------------------------------------------

#define NTPB 256
#define ETPB 256
constexpr int HD = 64;
constexpr int MAXN = 100000;

__device__ float g_m_u[(size_t)MAXN * HD];
__device__ float g_m_v[(size_t)MAXN * HD];
__device__ float g_deg[MAXN];

// ---- edge smem layout (in 4-byte words) -----------------------------------
constexpr int W1T_OFF = 0;                    // [128 n][192 k] tf32
constexpr int W2T_OFF = W1T_OFF + 128 * 192;  // [64 n][128 k] tf32
constexpr int X_OFF   = W2T_OFF + 64 * 128;   // [128 e][192 k] tf32 (H aliases)
constexpr int B1_OFF  = X_OFF + 128 * 192;    // 128 f32
constexpr int B2_OFF  = B1_OFF + 128;         // 64 f32
constexpr int EDGE_SMEM_WORDS = B2_OFF + 64;
constexpr int EDGE_SMEM = EDGE_SMEM_WORDS * 4;   // 230144 B

// ---- node smem layout (words) ---------------------------------------------
constexpr int NW1_OFF = 0;                    // [64 n][128 k] tf32
constexpr int NW2_OFF = NW1_OFF + 64 * 128;   // [64 n][64 k] tf32
constexpr int NX_OFF  = NW2_OFF + 64 * 64;    // [128 r][128 k] tf32 (H aliases)
constexpr int NB1_OFF = NX_OFF + 128 * 128;   // 64 f32
constexpr int NB2_OFF = NB1_OFF + 64;         // 64 f32
constexpr int NODE_SMEM = (NB2_OFF + 64) * 4; // 115712 B

__device__ __forceinline__ uint32_t f2tf(float f) {
    uint32_t r;
    asm("cvt.rna.tf32.f32 %0, %1;" : "=r"(r) : "f"(f));
    return r;
}

__device__ __forceinline__ void mma8(float* c, uint32_t a0, uint32_t a1,
                                     uint32_t a2, uint32_t a3,
                                     uint32_t b0, uint32_t b1) {
    asm("mma.sync.aligned.m16n8k8.row.col.f32.tf32.tf32.f32 "
        "{%0,%1,%2,%3}, {%4,%5,%6,%7}, {%8,%9}, {%0,%1,%2,%3};"
        : "+f"(c[0]), "+f"(c[1]), "+f"(c[2]), "+f"(c[3])
        : "r"(a0), "r"(a1), "r"(a2), "r"(a3), "r"(b0), "r"(b1));
}

// XOR-swizzled chunk store: row-stride in words, chunk = 16B unit index.
__device__ __forceinline__ void st_chunk(uint32_t* b, int row, int stride,
                                         int chunk, uint4 v) {
    const int c = (chunk & ~7) | ((chunk & 7) ^ (row & 7));
    *(uint4*)(b + row * stride + c * 4) = v;
}
__device__ __forceinline__ uint4 cvt4(float4 v) {
    uint4 r;
    r.x = f2tf(v.x); r.y = f2tf(v.y); r.z = f2tf(v.z); r.w = f2tf(v.w);
    return r;
}

// ---------------------------------------------------------------------------
// Edge MLP (mma.sync tf32):
//   x = [A[idxA[e]] | B[idxB[e]] | EF[e]] (192) -> relu(x@W1+b1) (128)
//     -> @W2+b2 (64) -> atomicAdd accum[idxOut[e]]
// Tile = 128 edges, 8 warps. GEMM1 warp: 32e x 64h. GEMM2 warp: 32e x 32o.
// ---------------------------------------------------------------------------
__global__ void __launch_bounds__(ETPB, 1) edge_mlp_tc(
    const float* __restrict__ A, const int* __restrict__ idxA,
    const float* __restrict__ B, const int* __restrict__ idxB,
    const float* __restrict__ EF, const int* __restrict__ idxOut,
    const float* __restrict__ W1, const float* __restrict__ b1,
    const float* __restrict__ W2, const float* __restrict__ b2,
    float* __restrict__ accum, float* __restrict__ deg, int E)
{
    extern __shared__ uint32_t smu[];
    uint32_t* W1s = smu + W1T_OFF;
    uint32_t* W2s = smu + W2T_OFF;
    uint32_t* Xs  = smu + X_OFF;
    uint32_t* Hs  = smu + X_OFF;           // aliases X (X dead after GEMM1)
    float* sB1 = (float*)(smu + B1_OFF);
    float* sB2 = (float*)(smu + B2_OFF);

    const int tid = threadIdx.x;
    const int warp = tid >> 5, lane = tid & 31;
    const int g = lane >> 2, t = lane & 3;

    // ---- one-time: weights transposed + tf32 + swizzled -------------------
    for (int i = tid; i < 128 * 192; i += ETPB) {
        const int n = i & 127, k = i >> 7;
        const int ch = k >> 2;
        const int cc = (ch & ~7) | ((ch & 7) ^ (n & 7));
        W1s[n * 192 + cc * 4 + (k & 3)] = f2tf(W1[k * 128 + n]);
    }
    for (int i = tid; i < 64 * 128; i += ETPB) {
        const int n = i & 63, k = i >> 6;
        const int ch = k >> 2;
        const int cc = (ch & ~7) | ((ch & 7) ^ (n & 7));
        W2s[n * 128 + cc * 4 + (k & 3)] = f2tf(W2[k * 64 + n]);
    }
    if (tid < 128) sB1[tid] = b1[tid];
    if (tid < 64)  sB2[tid] = b2[tid];
    __syncthreads();

    int off3[8];
    #pragma unroll
    for (int c = 0; c < 8; c++) off3[c] = ((c ^ g) << 2) + t;

    const int m0 = (warp >> 1) * 32;
    const int n0 = (warp & 1) * 64;
    const int nb = (warp & 1) * 32;

    int arA[2][2], arH[2][2], brB[8], br2[4];
    #pragma unroll
    for (int mi = 0; mi < 2; mi++) {
        arA[mi][0] = (m0 + mi * 16 + g) * 192;
        arA[mi][1] = (m0 + mi * 16 + g + 8) * 192;
        arH[mi][0] = (m0 + mi * 16 + g) * 128;
        arH[mi][1] = (m0 + mi * 16 + g + 8) * 128;
    }
    #pragma unroll
    for (int ni = 0; ni < 8; ni++) brB[ni] = (n0 + ni * 8 + g) * 192;
    #pragma unroll
    for (int ni = 0; ni < 4; ni++) br2[ni] = (nb + ni * 8 + g) * 128;

    const int el = tid >> 1, half = tid & 1;
    const int ntiles = (E + 127) >> 7;

    for (int tile = blockIdx.x; tile < ntiles; tile += gridDim.x) {
        const int base = tile << 7;

        // ---- stage X [128][192] gathered, tf32, swizzled ----
        {
            const int ge = base + el;
            if (ge < E) {
                if (half == 0) {
                    const float4* s = (const float4*)(A + (size_t)idxA[ge] * HD);
                    #pragma unroll
                    for (int j = 0; j < 16; j++)
                        st_chunk(Xs, el, 192, j, cvt4(s[j]));
                    const float4* e4 = (const float4*)(EF + (size_t)ge * HD);
                    #pragma unroll
                    for (int j = 0; j < 8; j++)
                        st_chunk(Xs, el, 192, 32 + j, cvt4(e4[j]));
                } else {
                    const float4* s = (const float4*)(B + (size_t)idxB[ge] * HD);
                    #pragma unroll
                    for (int j = 0; j < 16; j++)
                        st_chunk(Xs, el, 192, 16 + j, cvt4(s[j]));
                    const float4* e4 = (const float4*)(EF + (size_t)ge * HD);
                    #pragma unroll
                    for (int j = 0; j < 8; j++)
                        st_chunk(Xs, el, 192, 40 + j, cvt4(e4[8 + j]));
                }
            }
        }
        __syncthreads();

        // ---- GEMM1: 32e x 64h, K=192 ----
        float c1[2][8][4];
        #pragma unroll
        for (int mi = 0; mi < 2; mi++)
            #pragma unroll
            for (int ni = 0; ni < 8; ni++)
                #pragma unroll
                for (int q = 0; q < 4; q++) c1[mi][ni][q] = 0.0f;

        #pragma unroll
        for (int ks = 0; ks < 24; ks++) {
            const int C0 = 2 * ks, C1 = 2 * ks + 1;
            const int o0 = ((C0 & ~7) << 2) + off3[C0 & 7];
            const int o1 = ((C1 & ~7) << 2) + off3[C1 & 7];
            uint32_t a[2][4];
            #pragma unroll
            for (int mi = 0; mi < 2; mi++) {
                a[mi][0] = Xs[arA[mi][0] + o0];
                a[mi][1] = Xs[arA[mi][1] + o0];
                a[mi][2] = Xs[arA[mi][0] + o1];
                a[mi][3] = Xs[arA[mi][1] + o1];
            }
            uint32_t b[8][2];
            #pragma unroll
            for (int ni = 0; ni < 8; ni++) {
                b[ni][0] = W1s[brB[ni] + o0];
                b[ni][1] = W1s[brB[ni] + o1];
            }
            #pragma unroll
            for (int mi = 0; mi < 2; mi++)
                #pragma unroll
                for (int ni = 0; ni < 8; ni++)
                    mma8(c1[mi][ni], a[mi][0], a[mi][1], a[mi][2], a[mi][3],
                         b[ni][0], b[ni][1]);
        }
        __syncthreads();

        // ---- epilogue 1: relu(c1 + b1) -> H (tf32, swizzled) ----
        #pragma unroll
        for (int mi = 0; mi < 2; mi++) {
            const int r0 = m0 + mi * 16 + g;
            #pragma unroll
            for (int ni = 0; ni < 8; ni++) {
                const int col = n0 + ni * 8 + 2 * t;
                const float2 bb = *(const float2*)(sB1 + col);
                const int ch = col >> 2;
                const int cc = (ch & ~7) | ((ch & 7) ^ g);
                const int wo = cc * 4 + (col & 3);
                uint2 p;
                p.x = f2tf(fmaxf(c1[mi][ni][0] + bb.x, 0.0f));
                p.y = f2tf(fmaxf(c1[mi][ni][1] + bb.y, 0.0f));
                *(uint2*)(Hs + r0 * 128 + wo) = p;
                p.x = f2tf(fmaxf(c1[mi][ni][2] + bb.x, 0.0f));
                p.y = f2tf(fmaxf(c1[mi][ni][3] + bb.y, 0.0f));
                *(uint2*)(Hs + (r0 + 8) * 128 + wo) = p;
            }
        }
        if (deg != nullptr && tid < 128) {
            const int ge = base + tid;
            if (ge < E) atomicAdd(deg + idxA[ge], 1.0f);
        }
        __syncthreads();

        // ---- GEMM2: 32e x 32o, K=128 ----
        float c2[2][4][4];
        #pragma unroll
        for (int mi = 0; mi < 2; mi++)
            #pragma unroll
            for (int ni = 0; ni < 4; ni++)
                #pragma unroll
                for (int q = 0; q < 4; q++) c2[mi][ni][q] = 0.0f;

        #pragma unroll
        for (int ks = 0; ks < 16; ks++) {
            const int C0 = 2 * ks, C1 = 2 * ks + 1;
            const int o0 = ((C0 & ~7) << 2) + off3[C0 & 7];
            const int o1 = ((C1 & ~7) << 2) + off3[C1 & 7];
            uint32_t a[2][4];
            #pragma unroll
            for (int mi = 0; mi < 2; mi++) {
                a[mi][0] = Hs[arH[mi][0] + o0];
                a[mi][1] = Hs[arH[mi][1] + o0];
                a[mi][2] = Hs[arH[mi][0] + o1];
                a[mi][3] = Hs[arH[mi][1] + o1];
            }
            uint32_t b[4][2];
            #pragma unroll
            for (int ni = 0; ni < 4; ni++) {
                b[ni][0] = W2s[br2[ni] + o0];
                b[ni][1] = W2s[br2[ni] + o1];
            }
            #pragma unroll
            for (int mi = 0; mi < 2; mi++)
                #pragma unroll
                for (int ni = 0; ni < 4; ni++)
                    mma8(c2[mi][ni], a[mi][0], a[mi][1], a[mi][2], a[mi][3],
                         b[ni][0], b[ni][1]);
        }

        // ---- epilogue 2: + b2, atomic scatter ----
        #pragma unroll
        for (int mi = 0; mi < 2; mi++) {
            const int r0 = m0 + mi * 16 + g;
            const int ge0 = base + r0, ge1 = ge0 + 8;
            const int d0 = (ge0 < E) ? idxOut[ge0] : -1;
            const int d1 = (ge1 < E) ? idxOut[ge1] : -1;
            #pragma unroll
            for (int ni = 0; ni < 4; ni++) {
                const int col = nb + ni * 8 + 2 * t;
                const float2 bb = *(const float2*)(sB2 + col);
                if (d0 >= 0) {
                    float* p = accum + (size_t)d0 * HD + col;
                    atomicAdd(p,     c2[mi][ni][0] + bb.x);
                    atomicAdd(p + 1, c2[mi][ni][1] + bb.y);
                }
                if (d1 >= 0) {
                    float* p = accum + (size_t)d1 * HD + col;
                    atomicAdd(p,     c2[mi][ni][2] + bb.x);
                    atomicAdd(p + 1, c2[mi][ni][3] + bb.y);
                }
            }
        }
        __syncthreads();
    }
}

// ---------------------------------------------------------------------------
// Node MLP (mma.sync tf32):
//   x = [self[i] | msum[i]*scale] (128) -> relu(x@W1+b1) (64) -> @W2+b2 (64)
// Tile = 128 nodes, 8 warps, warp tile 32x32. H aliases X (stride 64).
// ---------------------------------------------------------------------------
__global__ void __launch_bounds__(NTPB, 1) node_mlp_tc(
    const float* __restrict__ selfF, const float* __restrict__ msum,
    const float* __restrict__ deg, const int* __restrict__ Sp,
    const float* __restrict__ W1, const float* __restrict__ b1,
    const float* __restrict__ W2, const float* __restrict__ b2,
    float* __restrict__ out, int N)
{
    extern __shared__ uint32_t smu[];
    uint32_t* W1s = smu + NW1_OFF;    // [64 n][128 k]
    uint32_t* W2s = smu + NW2_OFF;    // [64 n][64 k]
    uint32_t* Xs  = smu + NX_OFF;     // [128 r][128 k]
    uint32_t* Hs  = smu + NX_OFF;     // aliases X, stride 64
    float* sB1 = (float*)(smu + NB1_OFF);
    float* sB2 = (float*)(smu + NB2_OFF);

    const int tid = threadIdx.x;
    const int warp = tid >> 5, lane = tid & 31;
    const int g = lane >> 2, t = lane & 3;

    // weights: W1 [128k][64n] -> W1s[n][k] swizzled; W2 [64k][64n] -> W2s[n][k]
    for (int i = tid; i < 64 * 128; i += NTPB) {
        const int n = i & 63, k = i >> 6;
        const int ch = k >> 2;
        const int cc = (ch & ~7) | ((ch & 7) ^ (n & 7));
        W1s[n * 128 + cc * 4 + (k & 3)] = f2tf(W1[k * 64 + n]);
    }
    for (int i = tid; i < 64 * 64; i += NTPB) {
        const int n = i & 63, k = i >> 6;
        const int ch = k >> 2;
        const int cc = (ch & ~7) | ((ch & 7) ^ (n & 7));
        W2s[n * 64 + cc * 4 + (k & 3)] = f2tf(W2[k * 64 + n]);
    }
    if (tid < 64) { sB1[tid] = b1[tid]; sB2[tid] = b2[tid]; }
    __syncthreads();

    const float invS = (Sp != nullptr) ? (1.0f / (float)(*Sp)) : 0.0f;

    int off3[8];
    #pragma unroll
    for (int c = 0; c < 8; c++) off3[c] = ((c ^ g) << 2) + t;

    const int m0 = (warp >> 1) * 32;       // node rows of this warp
    const int n0 = (warp & 1) * 32;        // output cols (both GEMMs)

    int arX[2][2], arH[2][2], brB[4], br2[4];
    #pragma unroll
    for (int mi = 0; mi < 2; mi++) {
        arX[mi][0] = (m0 + mi * 16 + g) * 128;
        arX[mi][1] = (m0 + mi * 16 + g + 8) * 128;
        arH[mi][0] = (m0 + mi * 16 + g) * 64;
        arH[mi][1] = (m0 + mi * 16 + g + 8) * 64;
    }
    #pragma unroll
    for (int ni = 0; ni < 4; ni++) {
        brB[ni] = (n0 + ni * 8 + g) * 128;
        br2[ni] = (n0 + ni * 8 + g) * 64;
    }

    const int sr = tid >> 1, half = tid & 1;
    const int ntiles = (N + 127) >> 7;

    for (int tile = blockIdx.x; tile < ntiles; tile += gridDim.x) {
        const int base = tile << 7;

        // ---- stage X [128][128]: [self | msum*scale], tf32, swizzled ----
        {
            const int i = base + sr;
            if (i < N) {
                if (half == 0) {
                    const float4* s = (const float4*)(selfF + (size_t)i * HD);
                    #pragma unroll
                    for (int j = 0; j < 16; j++)
                        st_chunk(Xs, sr, 128, j, cvt4(s[j]));
                } else {
                    const float sc = (Sp != nullptr) ? invS
                                                     : (1.0f / fmaxf(deg[i], 1.0f));
                    const float4* m = (const float4*)(msum + (size_t)i * HD);
                    #pragma unroll
                    for (int j = 0; j < 16; j++) {
                        float4 v = m[j];
                        v.x *= sc; v.y *= sc; v.z *= sc; v.w *= sc;
                        st_chunk(Xs, sr, 128, 16 + j, cvt4(v));
                    }
                }
            }
        }
        __syncthreads();

        // ---- GEMM1: 32r x 32h, K=128 ----
        float c1[2][4][4];
        #pragma unroll
        for (int mi = 0; mi < 2; mi++)
            #pragma unroll
            for (int ni = 0; ni < 4; ni++)
                #pragma unroll
                for (int q = 0; q < 4; q++) c1[mi][ni][q] = 0.0f;

        #pragma unroll
        for (int ks = 0; ks < 16; ks++) {
            const int C0 = 2 * ks, C1 = 2 * ks + 1;
            const int o0 = ((C0 & ~7) << 2) + off3[C0 & 7];
            const int o1 = ((C1 & ~7) << 2) + off3[C1 & 7];
            uint32_t a[2][4];
            #pragma unroll
            for (int mi = 0; mi < 2; mi++) {
                a[mi][0] = Xs[arX[mi][0] + o0];
                a[mi][1] = Xs[arX[mi][1] + o0];
                a[mi][2] = Xs[arX[mi][0] + o1];
                a[mi][3] = Xs[arX[mi][1] + o1];
            }
            uint32_t b[4][2];
            #pragma unroll
            for (int ni = 0; ni < 4; ni++) {
                b[ni][0] = W1s[brB[ni] + o0];
                b[ni][1] = W1s[brB[ni] + o1];
            }
            #pragma unroll
            for (int mi = 0; mi < 2; mi++)
                #pragma unroll
                for (int ni = 0; ni < 4; ni++)
                    mma8(c1[mi][ni], a[mi][0], a[mi][1], a[mi][2], a[mi][3],
                         b[ni][0], b[ni][1]);
        }
        __syncthreads();   // X reads done (H aliases X)

        // ---- epilogue 1: relu(c1 + b1) -> H (tf32, swizzled, stride 64) ----
        #pragma unroll
        for (int mi = 0; mi < 2; mi++) {
            const int r0 = m0 + mi * 16 + g;
            #pragma unroll
            for (int ni = 0; ni < 4; ni++) {
                const int col = n0 + ni * 8 + 2 * t;
                const float2 bb = *(const float2*)(sB1 + col);
                const int ch = col >> 2;
                const int cc = (ch & ~7) | ((ch & 7) ^ g);
                const int wo = cc * 4 + (col & 3);
                uint2 p;
                p.x = f2tf(fmaxf(c1[mi][ni][0] + bb.x, 0.0f));
                p.y = f2tf(fmaxf(c1[mi][ni][1] + bb.y, 0.0f));
                *(uint2*)(Hs + r0 * 64 + wo) = p;
                p.x = f2tf(fmaxf(c1[mi][ni][2] + bb.x, 0.0f));
                p.y = f2tf(fmaxf(c1[mi][ni][3] + bb.y, 0.0f));
                *(uint2*)(Hs + (r0 + 8) * 64 + wo) = p;
            }
        }
        __syncthreads();

        // ---- GEMM2: 32r x 32o, K=64 ----
        float c2[2][4][4];
        #pragma unroll
        for (int mi = 0; mi < 2; mi++)
            #pragma unroll
            for (int ni = 0; ni < 4; ni++)
                #pragma unroll
                for (int q = 0; q < 4; q++) c2[mi][ni][q] = 0.0f;

        #pragma unroll
        for (int ks = 0; ks < 8; ks++) {
            const int C0 = 2 * ks, C1 = 2 * ks + 1;
            const int o0 = ((C0 & ~7) << 2) + off3[C0 & 7];
            const int o1 = ((C1 & ~7) << 2) + off3[C1 & 7];
            uint32_t a[2][4];
            #pragma unroll
            for (int mi = 0; mi < 2; mi++) {
                a[mi][0] = Hs[arH[mi][0] + o0];
                a[mi][1] = Hs[arH[mi][1] + o0];
                a[mi][2] = Hs[arH[mi][0] + o1];
                a[mi][3] = Hs[arH[mi][1] + o1];
            }
            uint32_t b[4][2];
            #pragma unroll
            for (int ni = 0; ni < 4; ni++) {
                b[ni][0] = W2s[br2[ni] + o0];
                b[ni][1] = W2s[br2[ni] + o1];
            }
            #pragma unroll
            for (int mi = 0; mi < 2; mi++)
                #pragma unroll
                for (int ni = 0; ni < 4; ni++)
                    mma8(c2[mi][ni], a[mi][0], a[mi][1], a[mi][2], a[mi][3],
                         b[ni][0], b[ni][1]);
        }

        // ---- epilogue 2: + b2, direct store ----
        #pragma unroll
        for (int mi = 0; mi < 2; mi++) {
            const int r0 = m0 + mi * 16 + g;
            const int gi0 = base + r0, gi1 = gi0 + 8;
            #pragma unroll
            for (int ni = 0; ni < 4; ni++) {
                const int col = n0 + ni * 8 + 2 * t;
                const float2 bb = *(const float2*)(sB2 + col);
                if (gi0 < N)
                    *(float2*)(out + (size_t)gi0 * HD + col) =
                        make_float2(c2[mi][ni][0] + bb.x, c2[mi][ni][1] + bb.y);
                if (gi1 < N)
                    *(float2*)(out + (size_t)gi1 * HD + col) =
                        make_float2(c2[mi][ni][2] + bb.x, c2[mi][ni][3] + bb.y);
            }
        }
        __syncthreads();   // H reads done before next tile staging
    }
}

// ---------------------------------------------------------------------------
extern "C" void kernel_launch(void* const* d_in, const int* in_sizes, int n_in,
                              void* d_out, int out_size)
{
    const float* h_v    = (const float*)d_in[0];
    const float* h_u    = (const float*)d_in[1];
    const float* e_feat = (const float*)d_in[2];
    const int*   ei     = (const int*)d_in[3];
    const int*   Sp     = (const int*)d_in[4];
    const float* a2u_w1 = (const float*)d_in[5];
    const float* a2u_b1 = (const float*)d_in[6];
    const float* a2u_w2 = (const float*)d_in[7];
    const float* a2u_b2 = (const float*)d_in[8];
    const float* u_w1   = (const float*)d_in[9];
    const float* u_b1   = (const float*)d_in[10];
    const float* u_w2   = (const float*)d_in[11];
    const float* u_b2   = (const float*)d_in[12];
    const float* u2a_w1 = (const float*)d_in[13];
    const float* u2a_b1 = (const float*)d_in[14];
    const float* u2a_w2 = (const float*)d_in[15];
    const float* u2a_b2 = (const float*)d_in[16];
    const float* a_w1   = (const float*)d_in[17];
    const float* a_b1   = (const float*)d_in[18];
    const float* a_w2   = (const float*)d_in[19];
    const float* a_b2   = (const float*)d_in[20];

    const int NVn = in_sizes[0] / HD;
    const int NUn = in_sizes[1] / HD;
    const int E   = in_sizes[3] / 2;
    const int* src = ei;
    const int* dst = ei + E;

    float *m_u = nullptr, *m_v = nullptr, *degp = nullptr;
    cudaGetSymbolAddress((void**)&m_u, g_m_u);
    cudaGetSymbolAddress((void**)&m_v, g_m_v);
    cudaGetSymbolAddress((void**)&degp, g_deg);

    int sms = 148;
    cudaDeviceGetAttribute(&sms, cudaDevAttrMultiProcessorCount, 0);

    cudaFuncSetAttribute(edge_mlp_tc,
                         cudaFuncAttributeMaxDynamicSharedMemorySize, EDGE_SMEM);
    cudaFuncSetAttribute(node_mlp_tc,
                         cudaFuncAttributeMaxDynamicSharedMemorySize, NODE_SMEM);

    cudaMemsetAsync(m_u,  0, (size_t)NUn * HD * sizeof(float));
    cudaMemsetAsync(m_v,  0, (size_t)NVn * HD * sizeof(float));
    cudaMemsetAsync(degp, 0, (size_t)NVn * sizeof(float));

    float* h_v_out = (float*)d_out;
    float* h_u_out = (float*)d_out + (size_t)NVn * HD;

    const int etiles = (E + 127) >> 7;
    const int egrid = etiles < sms ? etiles : sms;
    const int nutiles = (NUn + 127) >> 7;
    const int nvtiles = (NVn + 127) >> 7;
    const int ngrid_u = nutiles < sms ? nutiles : sms;
    const int ngrid_v = nvtiles < sms ? nvtiles : sms;

    // Pass 1: a -> u messages, scatter to m_u[dst]; count deg[src]
    edge_mlp_tc<<<egrid, ETPB, EDGE_SMEM>>>(
        h_v, src, h_u, dst, e_feat, dst,
        a2u_w1, a2u_b1, a2u_w2, a2u_b2, m_u, degp, E);

    // u node update
    node_mlp_tc<<<ngrid_u, NTPB, NODE_SMEM>>>(
        h_u, m_u, nullptr, Sp,
        u_w1, u_b1, u_w2, u_b2, h_u_out, NUn);

    // Pass 2: u -> a messages, scatter to m_v[src]
    edge_mlp_tc<<<egrid, ETPB, EDGE_SMEM>>>(
        h_u_out, dst, h_v, src, e_feat, src,
        u2a_w1, u2a_b1, u2a_w2, u2a_b2, m_v, nullptr, E);

    // v node update
    node_mlp_tc<<<ngrid_v, NTPB, NODE_SMEM>>>(
        h_v, m_v, degp, nullptr,
        a_w1, a_b1, a_w2, a_b2, h_v_out, NVn);
}

// round 9
// speedup vs baseline: 3.4312x; 1.3625x over previous
#include <cuda_runtime.h>
#include <cuda_fp16.h>
#include <cstdint>

// ---------------------------------------------------------------------------
// SparseMPNNLayer — all four MLPs via mma.sync m16n8k16 fp16 (fp32 accum).
//   pass1: msg = MLP([h_v[src], h_u[dst], e_feat]) -> atomic scatter m_u[dst]
//          deg[src] += 1
//   node1: h_u_out = MLP([h_u, m_u/S])
//   pass2: msg = MLP([h_u_out[dst], h_v[src], e_feat]) -> scatter m_v[src]
//   node2: h_v_out = MLP([h_v, m_v/max(deg,1)])
// ---------------------------------------------------------------------------

#define NTPB 256
#define ETPB 256
constexpr int HD = 64;
constexpr int MAXN = 100000;

__device__ float g_m_u[(size_t)MAXN * HD];
__device__ float g_m_v[(size_t)MAXN * HD];
__device__ float g_deg[MAXN];

// ---- edge smem layout (32-bit words; each word = 2 halves) ----------------
// rows: X/W1 stride 96 words (192 halves), H/W2 stride 64 words (128 halves)
constexpr int EW1_OFF = 0;                     // [128 n][192 k]h
constexpr int EW2_OFF = EW1_OFF + 128 * 96;    // [64 n][128 k]h
constexpr int EX_OFF  = EW2_OFF + 64 * 64;     // [128 e][192 k]h
constexpr int EH_OFF  = EX_OFF + 128 * 96;     // [128 e][128 h]h
constexpr int EB1_OFF = EH_OFF + 128 * 64;     // 128 f32
constexpr int EB2_OFF = EB1_OFF + 128;         // 64 f32
constexpr int EDGE_SMEM = (EB2_OFF + 64) * 4;  // 148224 B

// ---- node smem layout (words) ---------------------------------------------
constexpr int NW1_OFF = 0;                     // [64 n][128 k]h
constexpr int NW2_OFF = NW1_OFF + 64 * 64;     // [64 n][64 k]h
constexpr int NX_OFF  = NW2_OFF + 64 * 32;     // [128 r][128 k]h
constexpr int NH_OFF  = NX_OFF + 128 * 64;     // [128 r][64 h]h
constexpr int NB1_OFF = NH_OFF + 128 * 32;     // 64 f32
constexpr int NB2_OFF = NB1_OFF + 64;          // 64 f32
constexpr int NODE_SMEM = (NB2_OFF + 64) * 4;  // 74240 B

__device__ __forceinline__ uint32_t p2h(float a, float b) {
    __half2 h = __floats2half2_rn(a, b);   // low = a
    return *(uint32_t*)&h;
}
__device__ __forceinline__ uint4 pack8(float4 a, float4 b) {
    uint4 r;
    r.x = p2h(a.x, a.y); r.y = p2h(a.z, a.w);
    r.z = p2h(b.x, b.y); r.w = p2h(b.z, b.w);
    return r;
}

__device__ __forceinline__ void mma16(float* c, uint32_t a0, uint32_t a1,
                                      uint32_t a2, uint32_t a3,
                                      uint32_t b0, uint32_t b1) {
    asm("mma.sync.aligned.m16n8k16.row.col.f32.f16.f16.f32 "
        "{%0,%1,%2,%3}, {%4,%5,%6,%7}, {%8,%9}, {%0,%1,%2,%3};"
        : "+f"(c[0]), "+f"(c[1]), "+f"(c[2]), "+f"(c[3])
        : "r"(a0), "r"(a1), "r"(a2), "r"(a3), "r"(b0), "r"(b1));
}

// XOR-swizzled 16B-chunk store: row stride in words, chunk = 16B unit index.
__device__ __forceinline__ void st_chunk(uint32_t* b, int row, int stride,
                                         int chunk, uint4 v) {
    const int c = (chunk & ~7) | ((chunk & 7) ^ (row & 7));
    *(uint4*)(b + row * stride + c * 4) = v;
}

// ---------------------------------------------------------------------------
// Edge MLP: x = [A[idxA[e]] | B[idxB[e]] | EF[e]] (192) -> relu(x@W1+b1) (128)
//           -> @W2+b2 (64) -> atomicAdd accum[idxOut[e]]
// Tile = 128 edges, 8 warps. GEMM1 warp: 32e x 64h. GEMM2 warp: 32e x 32o.
// ---------------------------------------------------------------------------
__global__ void __launch_bounds__(ETPB, 1) edge_mlp_tc(
    const float* __restrict__ A, const int* __restrict__ idxA,
    const float* __restrict__ B, const int* __restrict__ idxB,
    const float* __restrict__ EF, const int* __restrict__ idxOut,
    const float* __restrict__ W1, const float* __restrict__ b1,
    const float* __restrict__ W2, const float* __restrict__ b2,
    float* __restrict__ accum, float* __restrict__ deg, int E)
{
    extern __shared__ uint32_t smu[];
    uint32_t* W1s = smu + EW1_OFF;
    uint32_t* W2s = smu + EW2_OFF;
    uint32_t* Xs  = smu + EX_OFF;
    uint32_t* Hs  = smu + EH_OFF;
    float* sB1 = (float*)(smu + EB1_OFF);
    float* sB2 = (float*)(smu + EB2_OFF);

    const int tid = threadIdx.x;
    const int warp = tid >> 5, lane = tid & 31;
    const int g = lane >> 2, t = lane & 3;

    // ---- one-time: weights -> [n][k] halves, swizzled ---------------------
    for (int i = tid; i < 96 * 128; i += ETPB) {
        const int kp = i >> 7, n = i & 127;               // kp: word (k-pair)
        const int ch = kp >> 2;
        const int cc = (ch & ~7) | ((ch & 7) ^ (n & 7));
        W1s[n * 96 + cc * 4 + (kp & 3)] =
            p2h(W1[(2 * kp) * 128 + n], W1[(2 * kp + 1) * 128 + n]);
    }
    for (int i = tid; i < 64 * 64; i += ETPB) {
        const int kp = i >> 6, n = i & 63;
        const int ch = kp >> 2;
        const int cc = (ch & ~7) | ((ch & 7) ^ (n & 7));
        W2s[n * 64 + cc * 4 + (kp & 3)] =
            p2h(W2[(2 * kp) * 64 + n], W2[(2 * kp + 1) * 64 + n]);
    }
    if (tid < 128) sB1[tid] = b1[tid];
    if (tid < 64)  sB2[tid] = b2[tid];
    __syncthreads();

    int off3[8];
    #pragma unroll
    for (int c = 0; c < 8; c++) off3[c] = ((c ^ g) << 2) + t;

    const int m0 = (warp >> 1) * 32;
    const int n0 = (warp & 1) * 64;
    const int nb = (warp & 1) * 32;

    int arA[2][2], arH[2][2], brB[8], br2[4];
    #pragma unroll
    for (int mi = 0; mi < 2; mi++) {
        arA[mi][0] = (m0 + mi * 16 + g) * 96;
        arA[mi][1] = (m0 + mi * 16 + g + 8) * 96;
        arH[mi][0] = (m0 + mi * 16 + g) * 64;
        arH[mi][1] = (m0 + mi * 16 + g + 8) * 64;
    }
    #pragma unroll
    for (int ni = 0; ni < 8; ni++) brB[ni] = (n0 + ni * 8 + g) * 96;
    #pragma unroll
    for (int ni = 0; ni < 4; ni++) br2[ni] = (nb + ni * 8 + g) * 64;

    const int el = tid >> 1, half = tid & 1;
    const int ntiles = (E + 127) >> 7;

    for (int tile = blockIdx.x; tile < ntiles; tile += gridDim.x) {
        const int base = tile << 7;

        // ---- stage X [128 rows][24 chunks]: gather, fp16, swizzled --------
        {
            const int ge = base + el;
            if (ge < E) {
                const float4* e4 = (const float4*)(EF + (size_t)ge * HD);
                if (half == 0) {
                    const float4* s = (const float4*)(A + (size_t)idxA[ge] * HD);
                    #pragma unroll
                    for (int j = 0; j < 8; j++)
                        st_chunk(Xs, el, 96, j, pack8(s[2 * j], s[2 * j + 1]));
                    #pragma unroll
                    for (int j = 0; j < 4; j++)
                        st_chunk(Xs, el, 96, 16 + j,
                                 pack8(e4[2 * j], e4[2 * j + 1]));
                } else {
                    const float4* s = (const float4*)(B + (size_t)idxB[ge] * HD);
                    #pragma unroll
                    for (int j = 0; j < 8; j++)
                        st_chunk(Xs, el, 96, 8 + j, pack8(s[2 * j], s[2 * j + 1]));
                    #pragma unroll
                    for (int j = 0; j < 4; j++)
                        st_chunk(Xs, el, 96, 20 + j,
                                 pack8(e4[8 + 2 * j], e4[9 + 2 * j]));
                }
            }
        }
        __syncthreads();   // (1) X ready

        // ---- GEMM1: 32e x 64h, K=192 (12 k16 steps) ----
        float c1[2][8][4];
        #pragma unroll
        for (int mi = 0; mi < 2; mi++)
            #pragma unroll
            for (int ni = 0; ni < 8; ni++)
                #pragma unroll
                for (int q = 0; q < 4; q++) c1[mi][ni][q] = 0.0f;

        #pragma unroll
        for (int ks = 0; ks < 12; ks++) {
            const int C0 = 2 * ks, C1 = 2 * ks + 1;
            const int o0 = ((C0 & ~7) << 2) + off3[C0 & 7];
            const int o1 = ((C1 & ~7) << 2) + off3[C1 & 7];
            uint32_t a[2][4];
            #pragma unroll
            for (int mi = 0; mi < 2; mi++) {
                a[mi][0] = Xs[arA[mi][0] + o0];
                a[mi][1] = Xs[arA[mi][1] + o0];
                a[mi][2] = Xs[arA[mi][0] + o1];
                a[mi][3] = Xs[arA[mi][1] + o1];
            }
            uint32_t b[8][2];
            #pragma unroll
            for (int ni = 0; ni < 8; ni++) {
                b[ni][0] = W1s[brB[ni] + o0];
                b[ni][1] = W1s[brB[ni] + o1];
            }
            #pragma unroll
            for (int mi = 0; mi < 2; mi++)
                #pragma unroll
                for (int ni = 0; ni < 8; ni++)
                    mma16(c1[mi][ni], a[mi][0], a[mi][1], a[mi][2], a[mi][3],
                          b[ni][0], b[ni][1]);
        }

        // ---- epilogue 1: relu(c1 + b1) -> H (fp16, swizzled) ----
        #pragma unroll
        for (int mi = 0; mi < 2; mi++) {
            const int r0 = m0 + mi * 16 + g;
            #pragma unroll
            for (int ni = 0; ni < 8; ni++) {
                const int col = n0 + ni * 8 + 2 * t;
                const float2 bb = *(const float2*)(sB1 + col);
                const int ch = (n0 >> 3) + ni;
                const int cc = (ch & ~7) | ((ch & 7) ^ g);
                const int wo = cc * 4 + t;
                Hs[r0 * 64 + wo] =
                    p2h(fmaxf(c1[mi][ni][0] + bb.x, 0.0f),
                        fmaxf(c1[mi][ni][1] + bb.y, 0.0f));
                Hs[(r0 + 8) * 64 + wo] =
                    p2h(fmaxf(c1[mi][ni][2] + bb.x, 0.0f),
                        fmaxf(c1[mi][ni][3] + bb.y, 0.0f));
            }
        }
        if (deg != nullptr && tid < 128) {
            const int ge = base + tid;
            if (ge < E) atomicAdd(deg + idxA[ge], 1.0f);
        }
        __syncthreads();   // (2) H ready

        // ---- GEMM2: 32e x 32o, K=128 (8 k16 steps) ----
        float c2[2][4][4];
        #pragma unroll
        for (int mi = 0; mi < 2; mi++)
            #pragma unroll
            for (int ni = 0; ni < 4; ni++)
                #pragma unroll
                for (int q = 0; q < 4; q++) c2[mi][ni][q] = 0.0f;

        #pragma unroll
        for (int ks = 0; ks < 8; ks++) {
            const int C0 = 2 * ks, C1 = 2 * ks + 1;
            const int o0 = ((C0 & ~7) << 2) + off3[C0 & 7];
            const int o1 = ((C1 & ~7) << 2) + off3[C1 & 7];
            uint32_t a[2][4];
            #pragma unroll
            for (int mi = 0; mi < 2; mi++) {
                a[mi][0] = Hs[arH[mi][0] + o0];
                a[mi][1] = Hs[arH[mi][1] + o0];
                a[mi][2] = Hs[arH[mi][0] + o1];
                a[mi][3] = Hs[arH[mi][1] + o1];
            }
            uint32_t b[4][2];
            #pragma unroll
            for (int ni = 0; ni < 4; ni++) {
                b[ni][0] = W2s[br2[ni] + o0];
                b[ni][1] = W2s[br2[ni] + o1];
            }
            #pragma unroll
            for (int mi = 0; mi < 2; mi++)
                #pragma unroll
                for (int ni = 0; ni < 4; ni++)
                    mma16(c2[mi][ni], a[mi][0], a[mi][1], a[mi][2], a[mi][3],
                          b[ni][0], b[ni][1]);
        }

        // ---- epilogue 2: + b2, atomic scatter ----
        #pragma unroll
        for (int mi = 0; mi < 2; mi++) {
            const int r0 = m0 + mi * 16 + g;
            const int ge0 = base + r0, ge1 = ge0 + 8;
            const int d0 = (ge0 < E) ? idxOut[ge0] : -1;
            const int d1 = (ge1 < E) ? idxOut[ge1] : -1;
            #pragma unroll
            for (int ni = 0; ni < 4; ni++) {
                const int col = nb + ni * 8 + 2 * t;
                const float2 bb = *(const float2*)(sB2 + col);
                if (d0 >= 0) {
                    float* p = accum + (size_t)d0 * HD + col;
                    atomicAdd(p,     c2[mi][ni][0] + bb.x);
                    atomicAdd(p + 1, c2[mi][ni][1] + bb.y);
                }
                if (d1 >= 0) {
                    float* p = accum + (size_t)d1 * HD + col;
                    atomicAdd(p,     c2[mi][ni][2] + bb.x);
                    atomicAdd(p + 1, c2[mi][ni][3] + bb.y);
                }
            }
        }
        // no barrier needed: next-tile X staging doesn't touch H, and the
        // next (1)-barrier orders everything else.
    }
}

// ---------------------------------------------------------------------------
// Node MLP: x = [self[i] | msum[i]*scale] (128) -> relu(x@W1+b1) (64)
//           -> @W2+b2 (64) -> direct store. 2 CTAs/SM.
// ---------------------------------------------------------------------------
__global__ void __launch_bounds__(NTPB, 2) node_mlp_tc(
    const float* __restrict__ selfF, const float* __restrict__ msum,
    const float* __restrict__ deg, const int* __restrict__ Sp,
    const float* __restrict__ W1, const float* __restrict__ b1,
    const float* __restrict__ W2, const float* __restrict__ b2,
    float* __restrict__ out, int N)
{
    extern __shared__ uint32_t smu[];
    uint32_t* W1s = smu + NW1_OFF;
    uint32_t* W2s = smu + NW2_OFF;
    uint32_t* Xs  = smu + NX_OFF;
    uint32_t* Hs  = smu + NH_OFF;
    float* sB1 = (float*)(smu + NB1_OFF);
    float* sB2 = (float*)(smu + NB2_OFF);

    const int tid = threadIdx.x;
    const int warp = tid >> 5, lane = tid & 31;
    const int g = lane >> 2, t = lane & 3;

    for (int i = tid; i < 64 * 64; i += NTPB) {
        const int kp = i >> 6, n = i & 63;
        const int ch = kp >> 2;
        const int cc = (ch & ~7) | ((ch & 7) ^ (n & 7));
        W1s[n * 64 + cc * 4 + (kp & 3)] =
            p2h(W1[(2 * kp) * 64 + n], W1[(2 * kp + 1) * 64 + n]);
    }
    for (int i = tid; i < 32 * 64; i += NTPB) {
        const int kp = i >> 6, n = i & 63;
        const int ch = kp >> 2;
        const int cc = (ch & ~7) | ((ch & 7) ^ (n & 7));
        W2s[n * 32 + cc * 4 + (kp & 3)] =
            p2h(W2[(2 * kp) * 64 + n], W2[(2 * kp + 1) * 64 + n]);
    }
    if (tid < 64) { sB1[tid] = b1[tid]; sB2[tid] = b2[tid]; }
    __syncthreads();

    const float invS = (Sp != nullptr) ? (1.0f / (float)(*Sp)) : 0.0f;

    int off3[8];
    #pragma unroll
    for (int c = 0; c < 8; c++) off3[c] = ((c ^ g) << 2) + t;

    const int m0 = (warp >> 1) * 32;
    const int n0 = (warp & 1) * 32;

    int arX[2][2], arH[2][2], brB[4], br2[4];
    #pragma unroll
    for (int mi = 0; mi < 2; mi++) {
        arX[mi][0] = (m0 + mi * 16 + g) * 64;
        arX[mi][1] = (m0 + mi * 16 + g + 8) * 64;
        arH[mi][0] = (m0 + mi * 16 + g) * 32;
        arH[mi][1] = (m0 + mi * 16 + g + 8) * 32;
    }
    #pragma unroll
    for (int ni = 0; ni < 4; ni++) {
        brB[ni] = (n0 + ni * 8 + g) * 64;
        br2[ni] = (n0 + ni * 8 + g) * 32;
    }

    const int sr = tid >> 1, half = tid & 1;
    const int ntiles = (N + 127) >> 7;

    for (int tile = blockIdx.x; tile < ntiles; tile += gridDim.x) {
        const int base = tile << 7;

        // ---- stage X [128 rows][16 chunks] ----
        {
            const int i = base + sr;
            if (i < N) {
                if (half == 0) {
                    const float4* s = (const float4*)(selfF + (size_t)i * HD);
                    #pragma unroll
                    for (int j = 0; j < 8; j++)
                        st_chunk(Xs, sr, 64, j, pack8(s[2 * j], s[2 * j + 1]));
                } else {
                    const float sc = (Sp != nullptr) ? invS
                                                     : (1.0f / fmaxf(deg[i], 1.0f));
                    const float4* m = (const float4*)(msum + (size_t)i * HD);
                    #pragma unroll
                    for (int j = 0; j < 8; j++) {
                        float4 v0 = m[2 * j], v1 = m[2 * j + 1];
                        v0.x *= sc; v0.y *= sc; v0.z *= sc; v0.w *= sc;
                        v1.x *= sc; v1.y *= sc; v1.z *= sc; v1.w *= sc;
                        st_chunk(Xs, sr, 64, 8 + j, pack8(v0, v1));
                    }
                }
            }
        }
        __syncthreads();   // (1) X ready

        // ---- GEMM1: 32r x 32h, K=128 (8 steps) ----
        float c1[2][4][4];
        #pragma unroll
        for (int mi = 0; mi < 2; mi++)
            #pragma unroll
            for (int ni = 0; ni < 4; ni++)
                #pragma unroll
                for (int q = 0; q < 4; q++) c1[mi][ni][q] = 0.0f;

        #pragma unroll
        for (int ks = 0; ks < 8; ks++) {
            const int C0 = 2 * ks, C1 = 2 * ks + 1;
            const int o0 = ((C0 & ~7) << 2) + off3[C0 & 7];
            const int o1 = ((C1 & ~7) << 2) + off3[C1 & 7];
            uint32_t a[2][4];
            #pragma unroll
            for (int mi = 0; mi < 2; mi++) {
                a[mi][0] = Xs[arX[mi][0] + o0];
                a[mi][1] = Xs[arX[mi][1] + o0];
                a[mi][2] = Xs[arX[mi][0] + o1];
                a[mi][3] = Xs[arX[mi][1] + o1];
            }
            uint32_t b[4][2];
            #pragma unroll
            for (int ni = 0; ni < 4; ni++) {
                b[ni][0] = W1s[brB[ni] + o0];
                b[ni][1] = W1s[brB[ni] + o1];
            }
            #pragma unroll
            for (int mi = 0; mi < 2; mi++)
                #pragma unroll
                for (int ni = 0; ni < 4; ni++)
                    mma16(c1[mi][ni], a[mi][0], a[mi][1], a[mi][2], a[mi][3],
                          b[ni][0], b[ni][1]);
        }

        // ---- epilogue 1: relu -> H (fp16, stride 32 words) ----
        #pragma unroll
        for (int mi = 0; mi < 2; mi++) {
            const int r0 = m0 + mi * 16 + g;
            #pragma unroll
            for (int ni = 0; ni < 4; ni++) {
                const int col = n0 + ni * 8 + 2 * t;
                const float2 bb = *(const float2*)(sB1 + col);
                const int ch = (n0 >> 3) + ni;
                const int cc = (ch & ~7) | ((ch & 7) ^ g);
                const int wo = cc * 4 + t;
                Hs[r0 * 32 + wo] =
                    p2h(fmaxf(c1[mi][ni][0] + bb.x, 0.0f),
                        fmaxf(c1[mi][ni][1] + bb.y, 0.0f));
                Hs[(r0 + 8) * 32 + wo] =
                    p2h(fmaxf(c1[mi][ni][2] + bb.x, 0.0f),
                        fmaxf(c1[mi][ni][3] + bb.y, 0.0f));
            }
        }
        __syncthreads();   // (2) H ready

        // ---- GEMM2: 32r x 32o, K=64 (4 steps) ----
        float c2[2][4][4];
        #pragma unroll
        for (int mi = 0; mi < 2; mi++)
            #pragma unroll
            for (int ni = 0; ni < 4; ni++)
                #pragma unroll
                for (int q = 0; q < 4; q++) c2[mi][ni][q] = 0.0f;

        #pragma unroll
        for (int ks = 0; ks < 4; ks++) {
            const int C0 = 2 * ks, C1 = 2 * ks + 1;
            const int o0 = ((C0 & ~7) << 2) + off3[C0 & 7];
            const int o1 = ((C1 & ~7) << 2) + off3[C1 & 7];
            uint32_t a[2][4];
            #pragma unroll
            for (int mi = 0; mi < 2; mi++) {
                a[mi][0] = Hs[arH[mi][0] + o0];
                a[mi][1] = Hs[arH[mi][1] + o0];
                a[mi][2] = Hs[arH[mi][0] + o1];
                a[mi][3] = Hs[arH[mi][1] + o1];
            }
            uint32_t b[4][2];
            #pragma unroll
            for (int ni = 0; ni < 4; ni++) {
                b[ni][0] = W2s[br2[ni] + o0];
                b[ni][1] = W2s[br2[ni] + o1];
            }
            #pragma unroll
            for (int mi = 0; mi < 2; mi++)
                #pragma unroll
                for (int ni = 0; ni < 4; ni++)
                    mma16(c2[mi][ni], a[mi][0], a[mi][1], a[mi][2], a[mi][3],
                          b[ni][0], b[ni][1]);
        }

        // ---- epilogue 2: + b2, direct store ----
        #pragma unroll
        for (int mi = 0; mi < 2; mi++) {
            const int r0 = m0 + mi * 16 + g;
            const int gi0 = base + r0, gi1 = gi0 + 8;
            #pragma unroll
            for (int ni = 0; ni < 4; ni++) {
                const int col = n0 + ni * 8 + 2 * t;
                const float2 bb = *(const float2*)(sB2 + col);
                if (gi0 < N)
                    *(float2*)(out + (size_t)gi0 * HD + col) =
                        make_float2(c2[mi][ni][0] + bb.x, c2[mi][ni][1] + bb.y);
                if (gi1 < N)
                    *(float2*)(out + (size_t)gi1 * HD + col) =
                        make_float2(c2[mi][ni][2] + bb.x, c2[mi][ni][3] + bb.y);
            }
        }
        // next-tile X staging doesn't touch H; ordering via next (1) barrier
    }
}

// ---------------------------------------------------------------------------
extern "C" void kernel_launch(void* const* d_in, const int* in_sizes, int n_in,
                              void* d_out, int out_size)
{
    const float* h_v    = (const float*)d_in[0];
    const float* h_u    = (const float*)d_in[1];
    const float* e_feat = (const float*)d_in[2];
    const int*   ei     = (const int*)d_in[3];
    const int*   Sp     = (const int*)d_in[4];
    const float* a2u_w1 = (const float*)d_in[5];
    const float* a2u_b1 = (const float*)d_in[6];
    const float* a2u_w2 = (const float*)d_in[7];
    const float* a2u_b2 = (const float*)d_in[8];
    const float* u_w1   = (const float*)d_in[9];
    const float* u_b1   = (const float*)d_in[10];
    const float* u_w2   = (const float*)d_in[11];
    const float* u_b2   = (const float*)d_in[12];
    const float* u2a_w1 = (const float*)d_in[13];
    const float* u2a_b1 = (const float*)d_in[14];
    const float* u2a_w2 = (const float*)d_in[15];
    const float* u2a_b2 = (const float*)d_in[16];
    const float* a_w1   = (const float*)d_in[17];
    const float* a_b1   = (const float*)d_in[18];
    const float* a_w2   = (const float*)d_in[19];
    const float* a_b2   = (const float*)d_in[20];

    const int NVn = in_sizes[0] / HD;
    const int NUn = in_sizes[1] / HD;
    const int E   = in_sizes[3] / 2;
    const int* src = ei;
    const int* dst = ei + E;

    float *m_u = nullptr, *m_v = nullptr, *degp = nullptr;
    cudaGetSymbolAddress((void**)&m_u, g_m_u);
    cudaGetSymbolAddress((void**)&m_v, g_m_v);
    cudaGetSymbolAddress((void**)&degp, g_deg);

    int sms = 148;
    cudaDeviceGetAttribute(&sms, cudaDevAttrMultiProcessorCount, 0);

    cudaFuncSetAttribute(edge_mlp_tc,
                         cudaFuncAttributeMaxDynamicSharedMemorySize, EDGE_SMEM);
    cudaFuncSetAttribute(node_mlp_tc,
                         cudaFuncAttributeMaxDynamicSharedMemorySize, NODE_SMEM);

    cudaMemsetAsync(m_u,  0, (size_t)NUn * HD * sizeof(float));
    cudaMemsetAsync(m_v,  0, (size_t)NVn * HD * sizeof(float));
    cudaMemsetAsync(degp, 0, (size_t)NVn * sizeof(float));

    float* h_v_out = (float*)d_out;
    float* h_u_out = (float*)d_out + (size_t)NVn * HD;

    const int etiles = (E + 127) >> 7;
    const int egrid = etiles < sms ? etiles : sms;
    const int nutiles = (NUn + 127) >> 7;
    const int nvtiles = (NVn + 127) >> 7;
    const int ngrid_u = nutiles < 2 * sms ? nutiles : 2 * sms;
    const int ngrid_v = nvtiles < 2 * sms ? nvtiles : 2 * sms;

    // Pass 1: a -> u messages, scatter to m_u[dst]; count deg[src]
    edge_mlp_tc<<<egrid, ETPB, EDGE_SMEM>>>(
        h_v, src, h_u, dst, e_feat, dst,
        a2u_w1, a2u_b1, a2u_w2, a2u_b2, m_u, degp, E);

    // u node update
    node_mlp_tc<<<ngrid_u, NTPB, NODE_SMEM>>>(
        h_u, m_u, nullptr, Sp,
        u_w1, u_b1, u_w2, u_b2, h_u_out, NUn);

    // Pass 2: u -> a messages, scatter to m_v[src]
    edge_mlp_tc<<<egrid, ETPB, EDGE_SMEM>>>(
        h_u_out, dst, h_v, src, e_feat, src,
        u2a_w1, u2a_b1, u2a_w2, u2a_b2, m_v, nullptr, E);

    // v node update
    node_mlp_tc<<<ngrid_v, NTPB, NODE_SMEM>>>(
        h_v, m_v, degp, nullptr,
        a_w1, a_b1, a_w2, a_b2, h_v_out, NVn);
}